// round 15
// baseline (speedup 1.0000x reference)
#include <cuda_runtime.h>
#include <cuda_bf16.h>
#include <math.h>
#include <stdint.h>

// ---------------- problem constants ----------------
#define NBATCH 4
#define NHEAD  8
#define BHN    (NBATCH*NHEAD)      // 32
#define NTOK   4096
#define CDIM   512
#define HD     64
#define MLAND  64
#define KSPLIT 16
#define SCALE  0.35355339059327373f   // 64^-0.25

// ---------------- device scratch ----------------
__device__ float g_Ql[BHN*MLAND*HD];
__device__ float g_Kl[BHN*MLAND*HD];
__device__ float g_K2[BHN*MLAND*MLAND];
__device__ float g_W [BHN*MLAND*HD];
__device__ float g_Tpart[KSPLIT*BHN*MLAND*HD];
__device__ float2 g_stats[BHN*MLAND*KSPLIT];
__device__ float g_colmax;

// bf16 hi/mid split buffers
__device__ __nv_bfloat16 g_xhi [16384*512];
__device__ __nv_bfloat16 g_xmid[16384*512];
__device__ __nv_bfloat16 g_whi [1536*512];
__device__ __nv_bfloat16 g_wmid[1536*512];
__device__ __nv_bfloat16 g_phi [512*512];
__device__ __nv_bfloat16 g_pmid[512*512];
__device__ __nv_bfloat16 g_Xhi [16384*512];
__device__ __nv_bfloat16 g_Xmid[16384*512];
__device__ __nv_bfloat16 g_Qhi [BHN*NTOK*HD];
__device__ __nv_bfloat16 g_Qmid[BHN*NTOK*HD];
__device__ __nv_bfloat16 g_Khi [BHN*NTOK*HD];
__device__ __nv_bfloat16 g_Kmid[BHN*NTOK*HD];
__device__ __nv_bfloat16 g_Vhi [BHN*NTOK*HD];
__device__ __nv_bfloat16 g_Vmid[BHN*NTOK*HD];
__device__ __nv_bfloat16 g_Qlh [BHN*MLAND*HD];
__device__ __nv_bfloat16 g_Qlm [BHN*MLAND*HD];
__device__ __nv_bfloat16 g_Klh [BHN*MLAND*HD];
__device__ __nv_bfloat16 g_Klm [BHN*MLAND*HD];
__device__ __nv_bfloat16 g_Whi [BHN*MLAND*HD];
__device__ __nv_bfloat16 g_Wmid[BHN*MLAND*HD];

// ==================== PTX helpers ====================
__device__ __forceinline__ uint32_t smem_u32(const void* p) {
    uint32_t a;
    asm("{ .reg .u64 t; cvta.to.shared.u64 t, %1; cvt.u32.u64 %0, t; }" : "=r"(a) : "l"(p));
    return a;
}
__device__ __forceinline__ void ldsm_x4(uint32_t& r0, uint32_t& r1, uint32_t& r2, uint32_t& r3,
                                        uint32_t addr) {
    asm volatile("ldmatrix.sync.aligned.m8n8.x4.shared.b16 {%0,%1,%2,%3}, [%4];"
                 : "=r"(r0), "=r"(r1), "=r"(r2), "=r"(r3) : "r"(addr));
}
__device__ __forceinline__ void ldsm_x4_t(uint32_t& r0, uint32_t& r1, uint32_t& r2, uint32_t& r3,
                                          uint32_t addr) {
    asm volatile("ldmatrix.sync.aligned.m8n8.x4.trans.shared.b16 {%0,%1,%2,%3}, [%4];"
                 : "=r"(r0), "=r"(r1), "=r"(r2), "=r"(r3) : "r"(addr));
}
__device__ __forceinline__ void mma16816(float* c, const uint32_t* a, const uint32_t* b) {
    asm volatile("mma.sync.aligned.m16n8k16.row.col.f32.bf16.bf16.f32 "
                 "{%0,%1,%2,%3}, {%4,%5,%6,%7}, {%8,%9}, {%0,%1,%2,%3};"
                 : "+f"(c[0]), "+f"(c[1]), "+f"(c[2]), "+f"(c[3])
                 : "r"(a[0]), "r"(a[1]), "r"(a[2]), "r"(a[3]), "r"(b[0]), "r"(b[1]));
}
#define CP_ASYNC(dst, src) asm volatile("cp.async.cg.shared.global [%0], [%1], 16;" :: "r"(dst), "l"(src))
#define CP_COMMIT()        asm volatile("cp.async.commit_group;" ::: "memory")
#define CP_WAIT1()         asm volatile("cp.async.wait_group 1;" ::: "memory")
#define CP_WAIT0()         asm volatile("cp.async.wait_group 0;" ::: "memory")

__device__ __forceinline__ void store_bf16_pair(__nv_bfloat16* hi, __nv_bfloat16* mid,
                                                float x, float y) {
    __nv_bfloat16 h0 = __float2bfloat16(x);
    __nv_bfloat16 h1 = __float2bfloat16(y);
    *(__nv_bfloat162*)hi = __nv_bfloat162(h0, h1);
    *(__nv_bfloat162*)mid = __nv_bfloat162(__float2bfloat16(x - __bfloat162float(h0)),
                                           __float2bfloat16(y - __bfloat162float(h1)));
}

// ==================== bf16 3x-split HMMA GEMM (big GEMMs) ====================
// y_eff = ya + blockIdx.y + (blockIdx.y>>4)*yb   (row-half pipelining)
#define PITCH 40
#define MAT_BYTES (128*PITCH*2)
#define SM_A_HI  0
#define SM_A_MID (1*MAT_BYTES)
#define SM_B_HI  (2*MAT_BYTES)
#define SM_B_MID (3*MAT_BYTES)
#define BUF_BYTES (4*MAT_BYTES)
#define GEMM_SMEM (2*BUF_BYTES)

__device__ __forceinline__ void load_stage(uint32_t bufb, int k0, size_t rowA0, size_t rowB0,
                                           const __nv_bfloat16* __restrict__ Ahi,
                                           const __nv_bfloat16* __restrict__ Amid,
                                           const __nv_bfloat16* __restrict__ Bhi,
                                           const __nv_bfloat16* __restrict__ Bmid,
                                           int tid) {
#pragma unroll
    for (int half = 0; half < 2; half++) {
        int c = tid + half * 256;
        int r = c >> 2, cc = (c & 3) * 8;
        uint32_t d = bufb + (uint32_t)(r * PITCH + cc) * 2;
        size_t goffA = (rowA0 + r) * 512 + k0 + cc;
        size_t goffB = (rowB0 + r) * 512 + k0 + cc;
        CP_ASYNC(d + SM_A_HI,  Ahi  + goffA);
        CP_ASYNC(d + SM_A_MID, Amid + goffA);
        CP_ASYNC(d + SM_B_HI,  Bhi  + goffB);
        CP_ASYNC(d + SM_B_MID, Bmid + goffB);
    }
    CP_COMMIT();
}

template<int MODE>
__global__ __launch_bounds__(256, 2) void hmma_gemm(
    const __nv_bfloat16* __restrict__ Ahi, const __nv_bfloat16* __restrict__ Amid,
    const __nv_bfloat16* __restrict__ Bhi, const __nv_bfloat16* __restrict__ Bmid,
    const float* __restrict__ bias, float* __restrict__ Cout, int ya, int yb)
{
    extern __shared__ __align__(128) char sm[];
    uint32_t sb = smem_u32(sm);
    int tid = threadIdx.x;
    int lane = tid & 31, wid = tid >> 5;
    int wm = wid >> 2, wn = wid & 3;
    int y_eff = ya + blockIdx.y + ((blockIdx.y >> 4) * yb);
    size_t rowA0 = (size_t)y_eff * 128;
    size_t rowB0 = (size_t)blockIdx.x * 128;

    float acc[4][4][4] = {};

    int arow  = wm * 64 + (lane & 15);
    int akoff = (lane >> 4) * 8;
    int brow  = wn * 32 + (lane & 7) + ((lane >> 4) << 3);
    int bkoff = ((lane >> 3) & 1) * 8;

    load_stage(sb, 0, rowA0, rowB0, Ahi, Amid, Bhi, Bmid, tid);

    for (int t = 0; t < 16; t++) {
        if (t + 1 < 16) {
            load_stage(sb + ((t + 1) & 1) * BUF_BYTES, (t + 1) * 32, rowA0, rowB0,
                       Ahi, Amid, Bhi, Bmid, tid);
            CP_WAIT1();
        } else {
            CP_WAIT0();
        }
        __syncthreads();

        uint32_t base = sb + (t & 1) * BUF_BYTES;
#pragma unroll
        for (int kk = 0; kk < 32; kk += 16) {
            uint32_t bhi[4][2], bmid[4][2];
#pragma unroll
            for (int np = 0; np < 2; np++) {
                uint32_t off = (uint32_t)((brow + np * 16) * PITCH + kk + bkoff) * 2;
                uint32_t r0, r1, r2, r3;
                ldsm_x4(r0, r1, r2, r3, base + SM_B_HI + off);
                bhi[np * 2][0] = r0; bhi[np * 2][1] = r1;
                bhi[np * 2 + 1][0] = r2; bhi[np * 2 + 1][1] = r3;
                ldsm_x4(r0, r1, r2, r3, base + SM_B_MID + off);
                bmid[np * 2][0] = r0; bmid[np * 2][1] = r1;
                bmid[np * 2 + 1][0] = r2; bmid[np * 2 + 1][1] = r3;
            }
#pragma unroll
            for (int mi = 0; mi < 4; mi++) {
                uint32_t ahi[4], amid[4];
                uint32_t off = (uint32_t)((arow + mi * 16) * PITCH + kk + akoff) * 2;
                ldsm_x4(ahi[0], ahi[1], ahi[2], ahi[3], base + SM_A_HI + off);
                ldsm_x4(amid[0], amid[1], amid[2], amid[3], base + SM_A_MID + off);
#pragma unroll
                for (int ni = 0; ni < 4; ni++) {
                    mma16816(acc[mi][ni], ahi, bhi[ni]);
                    mma16816(acc[mi][ni], ahi, bmid[ni]);
                    mma16816(acc[mi][ni], amid, bhi[ni]);
                }
            }
        }
        __syncthreads();
    }

    int colW = blockIdx.x * 128 + wn * 32 + 2 * (lane & 3);
    int rowW = y_eff * 128 + wm * 64 + (lane >> 2);
#pragma unroll
    for (int ni = 0; ni < 4; ni++) {
        int col = colW + ni * 8;
#pragma unroll
        for (int mi = 0; mi < 4; mi++) {
            int row0 = rowW + mi * 16;
            if (MODE == 0) {
                int which = col >> 9;
                int h = (col >> 6) & 7;
                int d = col & 63;
#pragma unroll
                for (int rr = 0; rr < 2; rr++) {
                    int row = row0 + rr * 8;
                    int b = row >> 12, n = row & 4095;
                    size_t idx = ((size_t)(b * 8 + h) * NTOK + n) * HD + d;
                    float vx = acc[mi][ni][rr * 2 + 0];
                    float vy = acc[mi][ni][rr * 2 + 1];
                    if (which == 0) {
                        store_bf16_pair(g_Qhi + idx, g_Qmid + idx, vx * SCALE, vy * SCALE);
                    } else if (which == 1) {
                        store_bf16_pair(g_Khi + idx, g_Kmid + idx, vx * SCALE, vy * SCALE);
                    } else {
                        store_bf16_pair(g_Vhi + idx, g_Vmid + idx, vx, vy);
                    }
                }
            } else {
                float2 bb = *(const float2*)(bias + col);
#pragma unroll
                for (int rr = 0; rr < 2; rr++) {
                    int row = row0 + rr * 8;
                    float2 v;
                    v.x = acc[mi][ni][rr * 2 + 0] + bb.x;
                    v.y = acc[mi][ni][rr * 2 + 1] + bb.y;
                    *(float2*)(Cout + (size_t)row * 512 + col) = v;
                }
            }
        }
    }
}

// ==================== fp32 -> bf16 hi/mid split ====================
__global__ void split_kernel(const float* __restrict__ src,
                             __nv_bfloat16* __restrict__ hi,
                             __nv_bfloat16* __restrict__ mid, int n4) {
    int i = blockIdx.x * 256 + threadIdx.x;
    if (i >= n4) return;
    float4 v = ((const float4*)src)[i];
    store_bf16_pair(hi + i * 4,     mid + i * 4,     v.x, v.y);
    store_bf16_pair(hi + i * 4 + 2, mid + i * 4 + 2, v.z, v.w);
}

// =====================================================================
// Landmark pooling (coalesced)
// =====================================================================
__device__ __forceinline__ void acc8(float* s, uint4 v) {
    const __nv_bfloat162* p = (const __nv_bfloat162*)&v;
#pragma unroll
    for (int j = 0; j < 4; j++) {
        float2 f = __bfloat1622float2(p[j]);
        s[j * 2 + 0] += f.x;
        s[j * 2 + 1] += f.y;
    }
}

__global__ void pool_kernel() {
    __shared__ float smq[8][64];
    __shared__ float smk[8][64];
    if (blockIdx.x == 0 && threadIdx.x == 0) g_colmax = 0.0f;
    int bm = blockIdx.x;
    int bh = bm >> 6, m = bm & 63;
    int tid = threadIdx.x;
    int grp = tid >> 3, ch = tid & 7;
    size_t rowbase = ((size_t)bh * NTOK + m * 64) * HD;
    float sq[8] = {}, sk[8] = {};
#pragma unroll
    for (int tt = 0; tt < 8; tt++) {
        size_t off = rowbase + (size_t)(grp * 8 + tt) * HD + ch * 8;
        acc8(sq, *(const uint4*)(g_Qhi + off));
        acc8(sq, *(const uint4*)(g_Qmid + off));
        acc8(sk, *(const uint4*)(g_Khi + off));
        acc8(sk, *(const uint4*)(g_Kmid + off));
    }
#pragma unroll
    for (int j = 0; j < 8; j++) {
        smq[grp][ch * 8 + j] = sq[j];
        smk[grp][ch * 8 + j] = sk[j];
    }
    __syncthreads();
    int d = tid;
    float q = 0.f, k = 0.f;
#pragma unroll
    for (int g = 0; g < 8; g++) { q += smq[g][d]; k += smk[g][d]; }
    float ql = q * (1.f / 64.f);
    float kl = k * (1.f / 64.f);
    int idx = (bh * 64 + m) * 64 + d;
    g_Ql[idx] = ql;
    g_Kl[idx] = kl;
    __nv_bfloat16 hq = __float2bfloat16(ql);
    g_Qlh[idx] = hq;
    g_Qlm[idx] = __float2bfloat16(ql - __bfloat162float(hq));
    __nv_bfloat16 hk = __float2bfloat16(kl);
    g_Klh[idx] = hk;
    g_Klm[idx] = __float2bfloat16(kl - __bfloat162float(hk));
}

// =====================================================================
// kernel_2 = softmax(Ql @ Kl^T) + colsum max
// =====================================================================
__global__ __launch_bounds__(256) void k2_kernel() {
    __shared__ float Qs[64][68];
    __shared__ float Ks[64][68];
    int bh = blockIdx.x, tid = threadIdx.x;
    for (int i = tid; i < 4096; i += 256) {
        Qs[i >> 6][i & 63] = g_Ql[bh * 4096 + i];
        Ks[i >> 6][i & 63] = g_Kl[bh * 4096 + i];
    }
    __syncthreads();
    int ty = tid >> 4, tx = tid & 15, r0 = ty * 4, c0 = tx * 4;
    float acc[4][4] = {};
    for (int k = 0; k < 64; k++) {
        float a[4], b[4];
#pragma unroll
        for (int i = 0; i < 4; i++) a[i] = Qs[r0 + i][k];
#pragma unroll
        for (int j = 0; j < 4; j++) b[j] = Ks[c0 + j][k];
#pragma unroll
        for (int i = 0; i < 4; i++)
#pragma unroll
            for (int j = 0; j < 4; j++) acc[i][j] = fmaf(a[i], b[j], acc[i][j]);
    }
    __syncthreads();
#pragma unroll
    for (int i = 0; i < 4; i++)
#pragma unroll
        for (int j = 0; j < 4; j++) Qs[r0 + i][c0 + j] = acc[i][j];
    __syncthreads();
    if (tid < 64) {
        float mx = -1e30f;
        for (int c = 0; c < 64; c++) mx = fmaxf(mx, Qs[tid][c]);
        float s = 0.f;
        for (int c = 0; c < 64; c++) { float e = __expf(Qs[tid][c] - mx); Qs[tid][c] = e; s += e; }
        float inv = 1.f / s;
        for (int c = 0; c < 64; c++) {
            float v = Qs[tid][c] * inv;
            Qs[tid][c] = v;
            g_K2[bh * 4096 + tid * 64 + c] = v;
        }
    }
    __syncthreads();
    if (tid < 64) {
        float cs = 0.f;
        for (int r = 0; r < 64; r++) cs += Qs[r][tid];
        atomicMax((int*)&g_colmax, __float_as_int(cs));
    }
}

// =====================================================================
// FUSED: S = Ql@K^T -> per-tile softmax stats -> P=exp(S-m_t) -> Tpart=P@V
// =====================================================================
#define AT_QPITCH 72
#define AT_PPITCH 264
#define AT_QH 0
#define AT_QM 9216
#define AT_KH 18432
#define AT_KM 55296
#define AT_PH 0
#define AT_PM 33792
#define AT_RED 92160
#define AT_VH 92160
#define AT_VM 101376
#define AT_SMEM 110592

__global__ __launch_bounds__(256, 2) void attn3_fused() {
    extern __shared__ __align__(128) char sm[];
    uint32_t sb = smem_u32(sm);
    float* s_red = (float*)(sm + AT_RED);
    float* s_rowmax = s_red + 64 * 9;
    int ks = blockIdx.x, bh = blockIdx.y, tid = threadIdx.x;
    int lane = tid & 31, wid = tid >> 5;

    const uint4* qh = (const uint4*)(g_Qlh + bh * 4096);
    const uint4* qm = (const uint4*)(g_Qlm + bh * 4096);
#pragma unroll
    for (int it = 0; it < 2; it++) {
        int c = tid + it * 256;
        int row = c >> 3, col = (c & 7) * 8;
        uint32_t off = (uint32_t)(row * AT_QPITCH + col) * 2;
        *(uint4*)(sm + AT_QH + off) = qh[c];
        *(uint4*)(sm + AT_QM + off) = qm[c];
    }
    const uint4* kh = (const uint4*)(g_Khi + ((size_t)bh * NTOK + ks * 256) * 64);
    const uint4* km = (const uint4*)(g_Kmid + ((size_t)bh * NTOK + ks * 256) * 64);
#pragma unroll
    for (int it = 0; it < 8; it++) {
        int c = tid + it * 256;
        int row = c >> 3, col = (c & 7) * 8;
        uint32_t off = (uint32_t)(row * AT_QPITCH + col) * 2;
        *(uint4*)(sm + AT_KH + off) = kh[c];
        *(uint4*)(sm + AT_KM + off) = km[c];
    }
    __syncthreads();

    int arow = lane & 15;
    int akoff = (lane >> 4) * 8;
    int brow = wid * 32 + (lane & 7) + ((lane >> 4) << 3);
    int bkoff = ((lane >> 3) & 1) * 8;

    float acc[4][4][4] = {};
#pragma unroll
    for (int kk = 0; kk < 64; kk += 16) {
        uint32_t bhi[4][2], bmid[4][2];
#pragma unroll
        for (int np = 0; np < 2; np++) {
            uint32_t off = (uint32_t)((brow + np * 16) * AT_QPITCH + kk + bkoff) * 2;
            uint32_t r0, r1, r2, r3;
            ldsm_x4(r0, r1, r2, r3, sb + AT_KH + off);
            bhi[np * 2][0] = r0; bhi[np * 2][1] = r1;
            bhi[np * 2 + 1][0] = r2; bhi[np * 2 + 1][1] = r3;
            ldsm_x4(r0, r1, r2, r3, sb + AT_KM + off);
            bmid[np * 2][0] = r0; bmid[np * 2][1] = r1;
            bmid[np * 2 + 1][0] = r2; bmid[np * 2 + 1][1] = r3;
        }
#pragma unroll
        for (int mi = 0; mi < 4; mi++) {
            uint32_t ahi[4], amid[4];
            uint32_t off = (uint32_t)((arow + mi * 16) * AT_QPITCH + kk + akoff) * 2;
            ldsm_x4(ahi[0], ahi[1], ahi[2], ahi[3], sb + AT_QH + off);
            ldsm_x4(amid[0], amid[1], amid[2], amid[3], sb + AT_QM + off);
#pragma unroll
            for (int ni = 0; ni < 4; ni++) {
                mma16816(acc[mi][ni], ahi, bhi[ni]);
                mma16816(acc[mi][ni], ahi, bmid[ni]);
                mma16816(acc[mi][ni], amid, bhi[ni]);
            }
        }
    }

#pragma unroll
    for (int mi = 0; mi < 4; mi++)
#pragma unroll
        for (int rr = 0; rr < 2; rr++) {
            float m = -1e30f;
#pragma unroll
            for (int ni = 0; ni < 4; ni++) {
                m = fmaxf(m, acc[mi][ni][rr * 2 + 0]);
                m = fmaxf(m, acc[mi][ni][rr * 2 + 1]);
            }
            m = fmaxf(m, __shfl_xor_sync(~0u, m, 1, 4));
            m = fmaxf(m, __shfl_xor_sync(~0u, m, 2, 4));
            if ((lane & 3) == 0)
                s_red[(mi * 16 + (lane >> 2) + rr * 8) * 9 + wid] = m;
        }
    __syncthreads();
    if (tid < 64) {
        float m = s_red[tid * 9];
#pragma unroll
        for (int w = 1; w < 8; w++) m = fmaxf(m, s_red[tid * 9 + w]);
        s_rowmax[tid] = m;
    }
    __syncthreads();

#pragma unroll
    for (int mi = 0; mi < 4; mi++)
#pragma unroll
        for (int rr = 0; rr < 2; rr++) {
            int row = mi * 16 + (lane >> 2) + rr * 8;
            float m = s_rowmax[row];
            float s = 0.f;
#pragma unroll
            for (int ni = 0; ni < 4; ni++) {
                float p0 = __expf(acc[mi][ni][rr * 2 + 0] - m);
                float p1 = __expf(acc[mi][ni][rr * 2 + 1] - m);
                acc[mi][ni][rr * 2 + 0] = p0;
                acc[mi][ni][rr * 2 + 1] = p1;
                s += p0 + p1;
            }
            s += __shfl_xor_sync(~0u, s, 1, 4);
            s += __shfl_xor_sync(~0u, s, 2, 4);
            if ((lane & 3) == 0) s_red[row * 9 + wid] = s;
        }
    __syncthreads();
    if (tid < 64) {
        float s = 0.f;
#pragma unroll
        for (int w = 0; w < 8; w++) s += s_red[tid * 9 + w];
        g_stats[((size_t)bh * 64 + tid) * KSPLIT + ks] = make_float2(s_rowmax[tid], s);
    }

    __syncthreads();
#pragma unroll
    for (int mi = 0; mi < 4; mi++)
#pragma unroll
        for (int ni = 0; ni < 4; ni++)
#pragma unroll
            for (int rr = 0; rr < 2; rr++) {
                int row = mi * 16 + (lane >> 2) + rr * 8;
                int col = wid * 32 + ni * 8 + 2 * (lane & 3);
                uint32_t off = (uint32_t)(row * AT_PPITCH + col) * 2;
                store_bf16_pair((__nv_bfloat16*)(sm + AT_PH + off),
                                (__nv_bfloat16*)(sm + AT_PM + off),
                                acc[mi][ni][rr * 2 + 0], acc[mi][ni][rr * 2 + 1]);
            }

    int wm = wid >> 2, wn = wid & 3;
    int arow2 = wm * 32 + (lane & 15);
    int bk = lane & 15;
    int bn = wn * 16 + ((lane >> 4) << 3);
    float acc2[2][2][4] = {};

    for (int kq = 0; kq < 4; kq++) {
        size_t gk = (size_t)ks * 256 + kq * 64;
        const uint4* vhp = (const uint4*)(g_Vhi + ((size_t)bh * NTOK + gk) * 64);
        const uint4* vmp = (const uint4*)(g_Vmid + ((size_t)bh * NTOK + gk) * 64);
        __syncthreads();
#pragma unroll
        for (int it = 0; it < 2; it++) {
            int c = tid + it * 256;
            int row = c >> 3, col = (c & 7) * 8;
            uint32_t off = (uint32_t)(row * AT_QPITCH + col) * 2;
            *(uint4*)(sm + AT_VH + off) = vhp[c];
            *(uint4*)(sm + AT_VM + off) = vmp[c];
        }
        __syncthreads();
#pragma unroll
        for (int kk = 0; kk < 64; kk += 16) {
            uint32_t bhi[2][2], bmid[2][2];
            {
                uint32_t off = (uint32_t)((kk + bk) * AT_QPITCH + bn) * 2;
                uint32_t r0, r1, r2, r3;
                ldsm_x4_t(r0, r1, r2, r3, sb + AT_VH + off);
                bhi[0][0] = r0; bhi[0][1] = r1; bhi[1][0] = r2; bhi[1][1] = r3;
                ldsm_x4_t(r0, r1, r2, r3, sb + AT_VM + off);
                bmid[0][0] = r0; bmid[0][1] = r1; bmid[1][0] = r2; bmid[1][1] = r3;
            }
#pragma unroll
            for (int mi = 0; mi < 2; mi++) {
                uint32_t ahi[4], amid[4];
                uint32_t off = (uint32_t)((arow2 + mi * 16) * AT_PPITCH
                                          + kq * 64 + kk + akoff) * 2;
                ldsm_x4(ahi[0], ahi[1], ahi[2], ahi[3], sb + AT_PH + off);
                ldsm_x4(amid[0], amid[1], amid[2], amid[3], sb + AT_PM + off);
#pragma unroll
                for (int ni = 0; ni < 2; ni++) {
                    mma16816(acc2[mi][ni], ahi, bhi[ni]);
                    mma16816(acc2[mi][ni], ahi, bmid[ni]);
                    mma16816(acc2[mi][ni], amid, bhi[ni]);
                }
            }
        }
    }
#pragma unroll
    for (int mi = 0; mi < 2; mi++)
#pragma unroll
        for (int ni = 0; ni < 2; ni++)
#pragma unroll
            for (int rr = 0; rr < 2; rr++) {
                int row = wm * 32 + mi * 16 + (lane >> 2) + rr * 8;
                int col = wn * 16 + ni * 8 + 2 * (lane & 3);
                float2 v;
                v.x = acc2[mi][ni][rr * 2 + 0];
                v.y = acc2[mi][ni][rr * 2 + 1];
                *(float2*)(g_Tpart + (((size_t)ks * BHN + bh) * 64 + row) * 64 + col) = v;
            }
}

// =====================================================================
// Newton-Schulz inverse on TENSOR CORES.  256 threads, 8 warps.
// =====================================================================
#define IM_PITCH 72
#define IM_MAT   18432
#define INV_SMEM (5*IM_MAT)

__device__ __forceinline__ void inv_mm(uint32_t sb, uint32_t oX, uint32_t oY,
                                       float acc[4][4], int lane, int wid) {
    int wm = wid >> 1, wn = wid & 1;
    int arow = wm * 16 + (lane & 15);
    int akoff = (lane >> 4) * 8;
    int bk = lane & 15;
    int bn = wn * 32 + ((lane >> 4) << 3);
#pragma unroll
    for (int kk = 0; kk < 64; kk += 16) {
        uint32_t bhi[4][2], bmid[4][2];
#pragma unroll
        for (int half = 0; half < 2; half++) {
            uint32_t off = (uint32_t)((kk + bk) * IM_PITCH + bn + half * 16) * 2;
            uint32_t r0, r1, r2, r3;
            ldsm_x4_t(r0, r1, r2, r3, sb + oY + off);
            bhi[half * 2][0] = r0; bhi[half * 2][1] = r1;
            bhi[half * 2 + 1][0] = r2; bhi[half * 2 + 1][1] = r3;
            ldsm_x4_t(r0, r1, r2, r3, sb + oY + 9216 + off);
            bmid[half * 2][0] = r0; bmid[half * 2][1] = r1;
            bmid[half * 2 + 1][0] = r2; bmid[half * 2 + 1][1] = r3;
        }
        uint32_t ahi[4], amid[4];
        uint32_t off = (uint32_t)(arow * IM_PITCH + kk + akoff) * 2;
        ldsm_x4(ahi[0], ahi[1], ahi[2], ahi[3], sb + oX + off);
        ldsm_x4(amid[0], amid[1], amid[2], amid[3], sb + oX + 9216 + off);
#pragma unroll
        for (int ni = 0; ni < 4; ni++) {
            mma16816(acc[ni], ahi, bhi[ni]);
            mma16816(acc[ni], ahi, bmid[ni]);
            mma16816(acc[ni], amid, bhi[ni]);
        }
    }
}

__device__ __forceinline__ void inv_store(char* sm, uint32_t oX, uint32_t oZ,
                                          const float acc[4][4],
                                          float alpha, float beta, int lane, int wid) {
    int wm = wid >> 1, wn = wid & 1;
#pragma unroll
    for (int ni = 0; ni < 4; ni++)
#pragma unroll
        for (int rr = 0; rr < 2; rr++) {
            int row = wm * 16 + (lane >> 2) + rr * 8;
            int col = wn * 32 + ni * 8 + 2 * (lane & 3);
            uint32_t off = (uint32_t)(row * IM_PITCH + col) * 2;
            float2 xh = __bfloat1622float2(*(__nv_bfloat162*)(sm + oX + off));
            float2 xm = __bfloat1622float2(*(__nv_bfloat162*)(sm + oX + 9216 + off));
            float z0 = alpha * (xh.x + xm.x) - beta * acc[ni][rr * 2 + 0];
            float z1 = alpha * (xh.y + xm.y) - beta * acc[ni][rr * 2 + 1];
            store_bf16_pair((__nv_bfloat16*)(sm + oZ + off),
                            (__nv_bfloat16*)(sm + oZ + 9216 + off), z0, z1);
        }
}

__global__ __launch_bounds__(256) void inv_kernel() {
    extern __shared__ __align__(128) char sm[];
    __shared__ float sc[64][17];
    __shared__ float sinv[64];
    uint32_t sb = smem_u32(sm);
    int bh = blockIdx.x, tid = threadIdx.x;
    int lane = tid & 31, wid = tid >> 5;
    float ginv = 1.f / g_colmax;

    uint32_t oK = 0, oV = IM_MAT, oA = 2 * IM_MAT, oTa = 3 * IM_MAT, oTb = 4 * IM_MAT;

    if (tid < 64) {
        int row = tid;
        float2 st[KSPLIT];
        float m = -1e30f;
#pragma unroll
        for (int t = 0; t < KSPLIT; t++) {
            st[t] = g_stats[((size_t)bh * 64 + row) * KSPLIT + t];
            m = fmaxf(m, st[t].x);
        }
        float sum = 0.f;
#pragma unroll
        for (int t = 0; t < KSPLIT; t++) {
            float e = __expf(st[t].x - m);
            sc[row][t] = e;
            sum += e * st[t].y;
        }
        sinv[row] = 1.f / sum;
    }
    __syncthreads();

    for (int i = tid * 2; i < 4096; i += 512) {
        int r = i >> 6, c = i & 63;
        uint32_t off = (uint32_t)(r * IM_PITCH + c) * 2;
        float k0 = g_K2[bh * 4096 + r * 64 + c];
        float k1 = g_K2[bh * 4096 + r * 64 + c + 1];
        store_bf16_pair((__nv_bfloat16*)(sm + oK + off),
                        (__nv_bfloat16*)(sm + oK + 9216 + off), k0, k1);
        float v0 = g_K2[bh * 4096 + c * 64 + r] * ginv;
        float v1 = g_K2[bh * 4096 + (c + 1) * 64 + r] * ginv;
        store_bf16_pair((__nv_bfloat16*)(sm + oV + off),
                        (__nv_bfloat16*)(sm + oV + 9216 + off), v0, v1);
    }
    for (int i = tid; i < 4096; i += 256) {
        int r = i >> 6;
        float s = 0.f;
#pragma unroll
        for (int t = 0; t < KSPLIT; t++)
            s = fmaf(g_Tpart[(size_t)t * (BHN * MLAND * HD) + bh * 4096 + i], sc[r][t], s);
        g_W[bh * 4096 + i] = s * sinv[r];
    }

    for (int it = 0; it < 6; it++) {
        __syncthreads();
        {
            float acc[4][4] = {};
            inv_mm(sb, oK, oV, acc, lane, wid);
            inv_store(sm, oK, oA, acc, 0.0f, -1.0f, lane, wid);
        }
        __syncthreads();
        {
            float acc[4][4] = {};
            inv_mm(sb, oA, oA, acc, lane, wid);
            inv_store(sm, oA, oTa, acc, 7.0f, 1.0f, lane, wid);
        }
        __syncthreads();
        {
            float acc[4][4] = {};
            inv_mm(sb, oA, oTa, acc, lane, wid);
            inv_store(sm, oA, oTb, acc, 15.0f, 1.0f, lane, wid);
        }
        __syncthreads();
        {
            float acc[4][4] = {};
            inv_mm(sb, oV, oTb, acc, lane, wid);
            inv_store(sm, oV, oTa, acc, 3.25f, 0.25f, lane, wid);
        }
        uint32_t tmp = oV; oV = oTa; oTa = tmp;
    }
    __syncthreads();

    for (int i = tid * 2; i < 4096; i += 512) {
        int r = i >> 6, c = i & 63;
        uint32_t off = (uint32_t)(r * IM_PITCH + c) * 2;
        float t0 = g_W[bh * 4096 + i];
        float t1 = g_W[bh * 4096 + i + 1];
        store_bf16_pair((__nv_bfloat16*)(sm + oK + off),
                        (__nv_bfloat16*)(sm + oK + 9216 + off), t0, t1);
    }
    __syncthreads();

    {
        float acc[4][4] = {};
        inv_mm(sb, oV, oK, acc, lane, wid);
        int wm = wid >> 1, wn = wid & 1;
#pragma unroll
        for (int ni = 0; ni < 4; ni++)
#pragma unroll
            for (int rr = 0; rr < 2; rr++) {
                int row = wm * 16 + (lane >> 2) + rr * 8;
                int col = wn * 32 + ni * 8 + 2 * (lane & 3);
                size_t idx = (size_t)bh * 4096 + row * 64 + col;
                store_bf16_pair(g_Whi + idx, g_Wmid + idx,
                                acc[ni][rr * 2 + 0], acc[ni][rr * 2 + 1]);
            }
    }
}

// =====================================================================
// Final fused via tensor cores (ntoff = n-tile offset for halves)
// =====================================================================
#define FA_PITCH 72
#define FA_QH 0
#define FA_QM (64*FA_PITCH*2)
#define FA_BH (2*64*FA_PITCH*2)
#define FA_BM (3*64*FA_PITCH*2)
#define FA_SS (4*64*FA_PITCH*2)
#define FA_SMEM (FA_SS + 64*68*4)

__global__ __launch_bounds__(256) void final_attn(int ntoff) {
    extern __shared__ __align__(128) char sm[];
    uint32_t sb = smem_u32(sm);
    float* Ss = (float*)(sm + FA_SS);
    int nt = blockIdx.x + ntoff, bh = blockIdx.y, tid = threadIdx.x;
    int lane = tid & 31, wid = tid >> 5;
    int wm = wid >> 1, wn = wid & 1;
    int b = bh >> 3, h = bh & 7;

    const uint4* qh = (const uint4*)(g_Qhi + (((size_t)bh * NTOK) + nt * 64) * 64);
    const uint4* qm = (const uint4*)(g_Qmid + (((size_t)bh * NTOK) + nt * 64) * 64);
    const uint4* kh = (const uint4*)(g_Klh + bh * 4096);
    const uint4* km = (const uint4*)(g_Klm + bh * 4096);
#pragma unroll
    for (int it = 0; it < 2; it++) {
        int c = tid + it * 256;
        int row = c >> 3, col = (c & 7) * 8;
        uint32_t off = (uint32_t)(row * FA_PITCH + col) * 2;
        *(uint4*)(sm + FA_QH + off) = qh[c];
        *(uint4*)(sm + FA_QM + off) = qm[c];
        *(uint4*)(sm + FA_BH + off) = kh[c];
        *(uint4*)(sm + FA_BM + off) = km[c];
    }
    __syncthreads();

    int arow = wm * 16 + (lane & 15);
    int akoff = (lane >> 4) * 8;
    int brow = wn * 32 + (lane & 7) + ((lane >> 4) << 3);
    int bkoff = ((lane >> 3) & 1) * 8;

    float acc[4][4] = {};
#pragma unroll
    for (int kk = 0; kk < 64; kk += 16) {
        uint32_t bhi[4][2], bmid[4][2];
#pragma unroll
        for (int np = 0; np < 2; np++) {
            uint32_t off = (uint32_t)((brow + np * 16) * FA_PITCH + kk + bkoff) * 2;
            uint32_t r0, r1, r2, r3;
            ldsm_x4(r0, r1, r2, r3, sb + FA_BH + off);
            bhi[np * 2][0] = r0; bhi[np * 2][1] = r1;
            bhi[np * 2 + 1][0] = r2; bhi[np * 2 + 1][1] = r3;
            ldsm_x4(r0, r1, r2, r3, sb + FA_BM + off);
            bmid[np * 2][0] = r0; bmid[np * 2][1] = r1;
            bmid[np * 2 + 1][0] = r2; bmid[np * 2 + 1][1] = r3;
        }
        uint32_t ahi[4], amid[4];
        uint32_t off = (uint32_t)(arow * FA_PITCH + kk + akoff) * 2;
        ldsm_x4(ahi[0], ahi[1], ahi[2], ahi[3], sb + FA_QH + off);
        ldsm_x4(amid[0], amid[1], amid[2], amid[3], sb + FA_QM + off);
#pragma unroll
        for (int ni = 0; ni < 4; ni++) {
            mma16816(acc[ni], ahi, bhi[ni]);
            mma16816(acc[ni], ahi, bmid[ni]);
            mma16816(acc[ni], amid, bhi[ni]);
        }
    }
#pragma unroll
    for (int ni = 0; ni < 4; ni++)
#pragma unroll
        for (int rr = 0; rr < 2; rr++) {
            int row = wm * 16 + (lane >> 2) + rr * 8;
            int col = wn * 32 + ni * 8 + 2 * (lane & 3);
            Ss[row * 68 + col] = acc[ni][rr * 2 + 0];
            Ss[row * 68 + col + 1] = acc[ni][rr * 2 + 1];
        }
    __syncthreads();

    const uint4* wh = (const uint4*)(g_Whi + bh * 4096);
    const uint4* wmv = (const uint4*)(g_Wmid + bh * 4096);
#pragma unroll
    for (int it = 0; it < 2; it++) {
        int c = tid + it * 256;
        int row = c >> 3, col = (c & 7) * 8;
        uint32_t off = (uint32_t)(row * FA_PITCH + col) * 2;
        *(uint4*)(sm + FA_BH + off) = wh[c];
        *(uint4*)(sm + FA_BM + off) = wmv[c];
    }

    {
        int r = tid >> 2;
        int c0 = (tid & 3) * 16;
        float v[16];
        float mx = -1e30f;
#pragma unroll
        for (int j = 0; j < 16; j++) { v[j] = Ss[r * 68 + c0 + j]; mx = fmaxf(mx, v[j]); }
        mx = fmaxf(mx, __shfl_xor_sync(~0u, mx, 1, 4));
        mx = fmaxf(mx, __shfl_xor_sync(~0u, mx, 2, 4));
        float s = 0.f;
#pragma unroll
        for (int j = 0; j < 16; j++) { v[j] = __expf(v[j] - mx); s += v[j]; }
        s += __shfl_xor_sync(~0u, s, 1, 4);
        s += __shfl_xor_sync(~0u, s, 2, 4);
        float inv = 1.f / s;
#pragma unroll
        for (int j = 0; j < 16; j += 2) {
            float p0 = v[j] * inv, p1 = v[j + 1] * inv;
            uint32_t off = (uint32_t)(r * FA_PITCH + c0 + j) * 2;
            store_bf16_pair((__nv_bfloat16*)(sm + FA_QH + off),
                            (__nv_bfloat16*)(sm + FA_QM + off), p0, p1);
        }
    }
    __syncthreads();

    int bk = lane & 15;
    int bn = wn * 32 + ((lane >> 4) << 3);
    float acc2[4][4] = {};
#pragma unroll
    for (int kk = 0; kk < 64; kk += 16) {
        uint32_t bhi[4][2], bmid[4][2];
#pragma unroll
        for (int half = 0; half < 2; half++) {
            uint32_t off = (uint32_t)((kk + bk) * FA_PITCH + bn + half * 16) * 2;
            uint32_t r0, r1, r2, r3;
            ldsm_x4_t(r0, r1, r2, r3, sb + FA_BH + off);
            bhi[half * 2][0] = r0; bhi[half * 2][1] = r1;
            bhi[half * 2 + 1][0] = r2; bhi[half * 2 + 1][1] = r3;
            ldsm_x4_t(r0, r1, r2, r3, sb + FA_BM + off);
            bmid[half * 2][0] = r0; bmid[half * 2][1] = r1;
            bmid[half * 2 + 1][0] = r2; bmid[half * 2 + 1][1] = r3;
        }
        uint32_t ahi[4], amid[4];
        uint32_t off = (uint32_t)(arow * FA_PITCH + kk + akoff) * 2;
        ldsm_x4(ahi[0], ahi[1], ahi[2], ahi[3], sb + FA_QH + off);
        ldsm_x4(amid[0], amid[1], amid[2], amid[3], sb + FA_QM + off);
#pragma unroll
        for (int ni = 0; ni < 4; ni++) {
            mma16816(acc2[ni], ahi, bhi[ni]);
            mma16816(acc2[ni], ahi, bmid[ni]);
            mma16816(acc2[ni], amid, bhi[ni]);
        }
    }
#pragma unroll
    for (int ni = 0; ni < 4; ni++)
#pragma unroll
        for (int rr = 0; rr < 2; rr++) {
            int row = wm * 16 + (lane >> 2) + rr * 8;
            int col = wn * 32 + ni * 8 + 2 * (lane & 3);
            size_t idx = (((size_t)b * NTOK) + nt * 64 + row) * CDIM + h * 64 + col;
            store_bf16_pair(g_Xhi + idx, g_Xmid + idx,
                            acc2[ni][rr * 2 + 0], acc2[ni][rr * 2 + 1]);
        }
}

// =====================================================================
// host launcher: head + tail half-pipelining
// =====================================================================
extern "C" void kernel_launch(void* const* d_in, const int* in_sizes, int n_in,
                              void* d_out, int out_size) {
    const float* x      = (const float*)d_in[0];
    const float* qkv_w  = (const float*)d_in[1];
    const float* proj_w = (const float*)d_in[2];
    const float* proj_b = (const float*)d_in[3];
    float* out = (float*)d_out;

    static cudaStream_t s2 = nullptr;
    static cudaEvent_t ev1 = nullptr, evW = nullptr, evX1 = nullptr,
                       ev3 = nullptr, ev4 = nullptr, evI = nullptr, evF1 = nullptr;
    if (s2 == nullptr) {
        cudaStreamCreateWithFlags(&s2, cudaStreamNonBlocking);
        cudaEventCreateWithFlags(&ev1, cudaEventDisableTiming);
        cudaEventCreateWithFlags(&evW, cudaEventDisableTiming);
        cudaEventCreateWithFlags(&evX1, cudaEventDisableTiming);
        cudaEventCreateWithFlags(&ev3, cudaEventDisableTiming);
        cudaEventCreateWithFlags(&ev4, cudaEventDisableTiming);
        cudaEventCreateWithFlags(&evI, cudaEventDisableTiming);
        cudaEventCreateWithFlags(&evF1, cudaEventDisableTiming);
    }

    __nv_bfloat16 *xhi, *xmid, *whi, *wmid, *phi, *pmid, *Xhi, *Xmid;
    cudaGetSymbolAddress((void**)&xhi,  g_xhi);
    cudaGetSymbolAddress((void**)&xmid, g_xmid);
    cudaGetSymbolAddress((void**)&whi,  g_whi);
    cudaGetSymbolAddress((void**)&wmid, g_wmid);
    cudaGetSymbolAddress((void**)&phi,  g_phi);
    cudaGetSymbolAddress((void**)&pmid, g_pmid);
    cudaGetSymbolAddress((void**)&Xhi,  g_Xhi);
    cudaGetSymbolAddress((void**)&Xmid, g_Xmid);

    cudaFuncSetAttribute(hmma_gemm<0>, cudaFuncAttributeMaxDynamicSharedMemorySize, GEMM_SMEM);
    cudaFuncSetAttribute(hmma_gemm<1>, cudaFuncAttributeMaxDynamicSharedMemorySize, GEMM_SMEM);
    cudaFuncSetAttribute(attn3_fused, cudaFuncAttributeMaxDynamicSharedMemorySize, AT_SMEM);
    cudaFuncSetAttribute(final_attn, cudaFuncAttributeMaxDynamicSharedMemorySize, FA_SMEM);
    cudaFuncSetAttribute(inv_kernel, cudaFuncAttributeMaxDynamicSharedMemorySize, INV_SMEM);

    const int XH_N4 = 8192 * 512 / 4;      // one half of x, in float4s
    const size_t XH_ELEM = (size_t)8192 * 512;

    // ---- head: x half0 (main) || {weights, x half1} (s2) ----
    cudaEventRecord(ev1, 0);
    cudaStreamWaitEvent(s2, ev1, 0);
    split_kernel<<<768, 256, 0, s2>>>(qkv_w, whi, wmid, 1536 * 512 / 4);
    split_kernel<<<256, 256, 0, s2>>>(proj_w, phi, pmid, 512 * 512 / 4);
    cudaEventRecord(evW, s2);
    split_kernel<<<4096, 256, 0, s2>>>(x + XH_ELEM, xhi + XH_ELEM, xmid + XH_ELEM, XH_N4);
    cudaEventRecord(evX1, s2);

    split_kernel<<<4096, 256>>>(x, xhi, xmid, XH_N4);
    cudaStreamWaitEvent(0, evW, 0);
    hmma_gemm<0><<<dim3(12, 64), 256, GEMM_SMEM>>>(xhi, xmid, whi, wmid,
                                                   nullptr, nullptr, 0, 0);
    cudaStreamWaitEvent(0, evX1, 0);
    hmma_gemm<0><<<dim3(12, 64), 256, GEMM_SMEM>>>(xhi, xmid, whi, wmid,
                                                   nullptr, nullptr, 64, 0);

    pool_kernel<<<BHN * MLAND, 64>>>();

    // ---- middle: k2 (s2) || attn3 (main) ----
    cudaEventRecord(ev3, 0);
    cudaStreamWaitEvent(s2, ev3, 0);
    k2_kernel<<<BHN, 256, 0, s2>>>();
    attn3_fused<<<dim3(KSPLIT, BHN), 256, AT_SMEM>>>();
    cudaEventRecord(ev4, s2);
    cudaStreamWaitEvent(0, ev4, 0);

    inv_kernel<<<BHN, 256, INV_SMEM>>>();
    cudaEventRecord(evI, 0);

    // ---- tail: final half1 (s2) || {final half0, hmma1 half0} (main) ----
    cudaStreamWaitEvent(s2, evI, 0);
    final_attn<<<dim3(32, BHN), 256, FA_SMEM, s2>>>(32);
    cudaEventRecord(evF1, s2);

    final_attn<<<dim3(32, BHN), 256, FA_SMEM>>>(0);
    hmma_gemm<1><<<dim3(4, 64), 256, GEMM_SMEM>>>(Xhi, Xmid, phi, pmid,
                                                  proj_b, out, 0, 16);
    cudaStreamWaitEvent(0, evF1, 0);
    hmma_gemm<1><<<dim3(4, 64), 256, GEMM_SMEM>>>(Xhi, Xmid, phi, pmid,
                                                  proj_b, out, 16, 16);
}

// round 16
// speedup vs baseline: 1.0608x; 1.0608x over previous
#include <cuda_runtime.h>
#include <cuda_bf16.h>
#include <math.h>
#include <stdint.h>

// ---------------- problem constants ----------------
#define NBATCH 4
#define NHEAD  8
#define BHN    (NBATCH*NHEAD)      // 32
#define NTOK   4096
#define CDIM   512
#define HD     64
#define MLAND  64
#define KSPLIT 16
#define SCALE  0.35355339059327373f   // 64^-0.25

// ---------------- device scratch ----------------
__device__ float g_Ql[BHN*MLAND*HD];
__device__ float g_Kl[BHN*MLAND*HD];
__device__ float g_K2[BHN*MLAND*MLAND];
__device__ float g_W [BHN*MLAND*HD];
__device__ float g_Tpart[KSPLIT*BHN*MLAND*HD];
__device__ float2 g_stats[BHN*MLAND*KSPLIT];
__device__ float g_colmax;

// bf16 hi/mid split buffers
__device__ __nv_bfloat16 g_xhi [16384*512];
__device__ __nv_bfloat16 g_xmid[16384*512];
__device__ __nv_bfloat16 g_whi [1536*512];
__device__ __nv_bfloat16 g_wmid[1536*512];
__device__ __nv_bfloat16 g_phi [512*512];
__device__ __nv_bfloat16 g_pmid[512*512];
__device__ __nv_bfloat16 g_Xhi [16384*512];
__device__ __nv_bfloat16 g_Xmid[16384*512];
__device__ __nv_bfloat16 g_Qhi [BHN*NTOK*HD];
__device__ __nv_bfloat16 g_Qmid[BHN*NTOK*HD];
__device__ __nv_bfloat16 g_Khi [BHN*NTOK*HD];
__device__ __nv_bfloat16 g_Kmid[BHN*NTOK*HD];
__device__ __nv_bfloat16 g_Vhi [BHN*NTOK*HD];
__device__ __nv_bfloat16 g_Vmid[BHN*NTOK*HD];
__device__ __nv_bfloat16 g_Qlh [BHN*MLAND*HD];
__device__ __nv_bfloat16 g_Qlm [BHN*MLAND*HD];
__device__ __nv_bfloat16 g_Klh [BHN*MLAND*HD];
__device__ __nv_bfloat16 g_Klm [BHN*MLAND*HD];
__device__ __nv_bfloat16 g_Whi [BHN*MLAND*HD];
__device__ __nv_bfloat16 g_Wmid[BHN*MLAND*HD];

// ==================== PTX helpers ====================
__device__ __forceinline__ uint32_t smem_u32(const void* p) {
    uint32_t a;
    asm("{ .reg .u64 t; cvta.to.shared.u64 t, %1; cvt.u32.u64 %0, t; }" : "=r"(a) : "l"(p));
    return a;
}
__device__ __forceinline__ void ldsm_x4(uint32_t& r0, uint32_t& r1, uint32_t& r2, uint32_t& r3,
                                        uint32_t addr) {
    asm volatile("ldmatrix.sync.aligned.m8n8.x4.shared.b16 {%0,%1,%2,%3}, [%4];"
                 : "=r"(r0), "=r"(r1), "=r"(r2), "=r"(r3) : "r"(addr));
}
__device__ __forceinline__ void ldsm_x4_t(uint32_t& r0, uint32_t& r1, uint32_t& r2, uint32_t& r3,
                                          uint32_t addr) {
    asm volatile("ldmatrix.sync.aligned.m8n8.x4.trans.shared.b16 {%0,%1,%2,%3}, [%4];"
                 : "=r"(r0), "=r"(r1), "=r"(r2), "=r"(r3) : "r"(addr));
}
__device__ __forceinline__ void mma16816(float* c, const uint32_t* a, const uint32_t* b) {
    asm volatile("mma.sync.aligned.m16n8k16.row.col.f32.bf16.bf16.f32 "
                 "{%0,%1,%2,%3}, {%4,%5,%6,%7}, {%8,%9}, {%0,%1,%2,%3};"
                 : "+f"(c[0]), "+f"(c[1]), "+f"(c[2]), "+f"(c[3])
                 : "r"(a[0]), "r"(a[1]), "r"(a[2]), "r"(a[3]), "r"(b[0]), "r"(b[1]));
}
#define CP_ASYNC(dst, src) asm volatile("cp.async.cg.shared.global [%0], [%1], 16;" :: "r"(dst), "l"(src))
#define CP_COMMIT()        asm volatile("cp.async.commit_group;" ::: "memory")
#define CP_WAIT1()         asm volatile("cp.async.wait_group 1;" ::: "memory")
#define CP_WAIT0()         asm volatile("cp.async.wait_group 0;" ::: "memory")

__device__ __forceinline__ void store_bf16_pair(__nv_bfloat16* hi, __nv_bfloat16* mid,
                                                float x, float y) {
    __nv_bfloat16 h0 = __float2bfloat16(x);
    __nv_bfloat16 h1 = __float2bfloat16(y);
    *(__nv_bfloat162*)hi = __nv_bfloat162(h0, h1);
    *(__nv_bfloat162*)mid = __nv_bfloat162(__float2bfloat16(x - __bfloat162float(h0)),
                                           __float2bfloat16(y - __bfloat162float(h1)));
}

// ==================== bf16 3x-split HMMA GEMM (big GEMMs) ====================
#define PITCH 40
#define MAT_BYTES (128*PITCH*2)
#define SM_A_HI  0
#define SM_A_MID (1*MAT_BYTES)
#define SM_B_HI  (2*MAT_BYTES)
#define SM_B_MID (3*MAT_BYTES)
#define BUF_BYTES (4*MAT_BYTES)
#define GEMM_SMEM (2*BUF_BYTES)

__device__ __forceinline__ void load_stage(uint32_t bufb, int k0, size_t rowA0, size_t rowB0,
                                           const __nv_bfloat16* __restrict__ Ahi,
                                           const __nv_bfloat16* __restrict__ Amid,
                                           const __nv_bfloat16* __restrict__ Bhi,
                                           const __nv_bfloat16* __restrict__ Bmid,
                                           int tid) {
#pragma unroll
    for (int half = 0; half < 2; half++) {
        int c = tid + half * 256;
        int r = c >> 2, cc = (c & 3) * 8;
        uint32_t d = bufb + (uint32_t)(r * PITCH + cc) * 2;
        size_t goffA = (rowA0 + r) * 512 + k0 + cc;
        size_t goffB = (rowB0 + r) * 512 + k0 + cc;
        CP_ASYNC(d + SM_A_HI,  Ahi  + goffA);
        CP_ASYNC(d + SM_A_MID, Amid + goffA);
        CP_ASYNC(d + SM_B_HI,  Bhi  + goffB);
        CP_ASYNC(d + SM_B_MID, Bmid + goffB);
    }
    CP_COMMIT();
}

template<int MODE>
__global__ __launch_bounds__(256, 2) void hmma_gemm(
    const __nv_bfloat16* __restrict__ Ahi, const __nv_bfloat16* __restrict__ Amid,
    const __nv_bfloat16* __restrict__ Bhi, const __nv_bfloat16* __restrict__ Bmid,
    const float* __restrict__ bias, float* __restrict__ Cout, int ya)
{
    extern __shared__ __align__(128) char sm[];
    uint32_t sb = smem_u32(sm);
    int tid = threadIdx.x;
    int lane = tid & 31, wid = tid >> 5;
    int wm = wid >> 2, wn = wid & 3;
    int y_eff = ya + blockIdx.y;
    size_t rowA0 = (size_t)y_eff * 128;
    size_t rowB0 = (size_t)blockIdx.x * 128;

    float acc[4][4][4] = {};

    int arow  = wm * 64 + (lane & 15);
    int akoff = (lane >> 4) * 8;
    int brow  = wn * 32 + (lane & 7) + ((lane >> 4) << 3);
    int bkoff = ((lane >> 3) & 1) * 8;

    load_stage(sb, 0, rowA0, rowB0, Ahi, Amid, Bhi, Bmid, tid);

    for (int t = 0; t < 16; t++) {
        if (t + 1 < 16) {
            load_stage(sb + ((t + 1) & 1) * BUF_BYTES, (t + 1) * 32, rowA0, rowB0,
                       Ahi, Amid, Bhi, Bmid, tid);
            CP_WAIT1();
        } else {
            CP_WAIT0();
        }
        __syncthreads();

        uint32_t base = sb + (t & 1) * BUF_BYTES;
#pragma unroll
        for (int kk = 0; kk < 32; kk += 16) {
            uint32_t bhi[4][2], bmid[4][2];
#pragma unroll
            for (int np = 0; np < 2; np++) {
                uint32_t off = (uint32_t)((brow + np * 16) * PITCH + kk + bkoff) * 2;
                uint32_t r0, r1, r2, r3;
                ldsm_x4(r0, r1, r2, r3, base + SM_B_HI + off);
                bhi[np * 2][0] = r0; bhi[np * 2][1] = r1;
                bhi[np * 2 + 1][0] = r2; bhi[np * 2 + 1][1] = r3;
                ldsm_x4(r0, r1, r2, r3, base + SM_B_MID + off);
                bmid[np * 2][0] = r0; bmid[np * 2][1] = r1;
                bmid[np * 2 + 1][0] = r2; bmid[np * 2 + 1][1] = r3;
            }
#pragma unroll
            for (int mi = 0; mi < 4; mi++) {
                uint32_t ahi[4], amid[4];
                uint32_t off = (uint32_t)((arow + mi * 16) * PITCH + kk + akoff) * 2;
                ldsm_x4(ahi[0], ahi[1], ahi[2], ahi[3], base + SM_A_HI + off);
                ldsm_x4(amid[0], amid[1], amid[2], amid[3], base + SM_A_MID + off);
#pragma unroll
                for (int ni = 0; ni < 4; ni++) {
                    mma16816(acc[mi][ni], ahi, bhi[ni]);
                    mma16816(acc[mi][ni], ahi, bmid[ni]);
                    mma16816(acc[mi][ni], amid, bhi[ni]);
                }
            }
        }
        __syncthreads();
    }

    int colW = blockIdx.x * 128 + wn * 32 + 2 * (lane & 3);
    int rowW = y_eff * 128 + wm * 64 + (lane >> 2);
#pragma unroll
    for (int ni = 0; ni < 4; ni++) {
        int col = colW + ni * 8;
#pragma unroll
        for (int mi = 0; mi < 4; mi++) {
            int row0 = rowW + mi * 16;
            if (MODE == 0) {
                int which = col >> 9;
                int h = (col >> 6) & 7;
                int d = col & 63;
#pragma unroll
                for (int rr = 0; rr < 2; rr++) {
                    int row = row0 + rr * 8;
                    int b = row >> 12, n = row & 4095;
                    size_t idx = ((size_t)(b * 8 + h) * NTOK + n) * HD + d;
                    float vx = acc[mi][ni][rr * 2 + 0];
                    float vy = acc[mi][ni][rr * 2 + 1];
                    if (which == 0) {
                        store_bf16_pair(g_Qhi + idx, g_Qmid + idx, vx * SCALE, vy * SCALE);
                    } else if (which == 1) {
                        store_bf16_pair(g_Khi + idx, g_Kmid + idx, vx * SCALE, vy * SCALE);
                    } else {
                        store_bf16_pair(g_Vhi + idx, g_Vmid + idx, vx, vy);
                    }
                }
            } else {
                float2 bb = *(const float2*)(bias + col);
#pragma unroll
                for (int rr = 0; rr < 2; rr++) {
                    int row = row0 + rr * 8;
                    float2 v;
                    v.x = acc[mi][ni][rr * 2 + 0] + bb.x;
                    v.y = acc[mi][ni][rr * 2 + 1] + bb.y;
                    *(float2*)(Cout + (size_t)row * 512 + col) = v;
                }
            }
        }
    }
}

// ==================== fp32 -> bf16 hi/mid split ====================
__global__ void split_kernel(const float* __restrict__ src,
                             __nv_bfloat16* __restrict__ hi,
                             __nv_bfloat16* __restrict__ mid, int n4) {
    int i = blockIdx.x * 256 + threadIdx.x;
    if (i >= n4) return;
    float4 v = ((const float4*)src)[i];
    store_bf16_pair(hi + i * 4,     mid + i * 4,     v.x, v.y);
    store_bf16_pair(hi + i * 4 + 2, mid + i * 4 + 2, v.z, v.w);
}

// =====================================================================
// Landmark pooling (coalesced)
// =====================================================================
__device__ __forceinline__ void acc8(float* s, uint4 v) {
    const __nv_bfloat162* p = (const __nv_bfloat162*)&v;
#pragma unroll
    for (int j = 0; j < 4; j++) {
        float2 f = __bfloat1622float2(p[j]);
        s[j * 2 + 0] += f.x;
        s[j * 2 + 1] += f.y;
    }
}

__global__ void pool_kernel() {
    __shared__ float smq[8][64];
    __shared__ float smk[8][64];
    if (blockIdx.x == 0 && threadIdx.x == 0) g_colmax = 0.0f;
    int bm = blockIdx.x;
    int bh = bm >> 6, m = bm & 63;
    int tid = threadIdx.x;
    int grp = tid >> 3, ch = tid & 7;
    size_t rowbase = ((size_t)bh * NTOK + m * 64) * HD;
    float sq[8] = {}, sk[8] = {};
#pragma unroll
    for (int tt = 0; tt < 8; tt++) {
        size_t off = rowbase + (size_t)(grp * 8 + tt) * HD + ch * 8;
        acc8(sq, *(const uint4*)(g_Qhi + off));
        acc8(sq, *(const uint4*)(g_Qmid + off));
        acc8(sk, *(const uint4*)(g_Khi + off));
        acc8(sk, *(const uint4*)(g_Kmid + off));
    }
#pragma unroll
    for (int j = 0; j < 8; j++) {
        smq[grp][ch * 8 + j] = sq[j];
        smk[grp][ch * 8 + j] = sk[j];
    }
    __syncthreads();
    int d = tid;
    float q = 0.f, k = 0.f;
#pragma unroll
    for (int g = 0; g < 8; g++) { q += smq[g][d]; k += smk[g][d]; }
    float ql = q * (1.f / 64.f);
    float kl = k * (1.f / 64.f);
    int idx = (bh * 64 + m) * 64 + d;
    g_Ql[idx] = ql;
    g_Kl[idx] = kl;
    __nv_bfloat16 hq = __float2bfloat16(ql);
    g_Qlh[idx] = hq;
    g_Qlm[idx] = __float2bfloat16(ql - __bfloat162float(hq));
    __nv_bfloat16 hk = __float2bfloat16(kl);
    g_Klh[idx] = hk;
    g_Klm[idx] = __float2bfloat16(kl - __bfloat162float(hk));
}

// =====================================================================
// kernel_2 = softmax(Ql @ Kl^T) + colsum max
// =====================================================================
__global__ __launch_bounds__(256) void k2_kernel() {
    __shared__ float Qs[64][68];
    __shared__ float Ks[64][68];
    int bh = blockIdx.x, tid = threadIdx.x;
    for (int i = tid; i < 4096; i += 256) {
        Qs[i >> 6][i & 63] = g_Ql[bh * 4096 + i];
        Ks[i >> 6][i & 63] = g_Kl[bh * 4096 + i];
    }
    __syncthreads();
    int ty = tid >> 4, tx = tid & 15, r0 = ty * 4, c0 = tx * 4;
    float acc[4][4] = {};
    for (int k = 0; k < 64; k++) {
        float a[4], b[4];
#pragma unroll
        for (int i = 0; i < 4; i++) a[i] = Qs[r0 + i][k];
#pragma unroll
        for (int j = 0; j < 4; j++) b[j] = Ks[c0 + j][k];
#pragma unroll
        for (int i = 0; i < 4; i++)
#pragma unroll
            for (int j = 0; j < 4; j++) acc[i][j] = fmaf(a[i], b[j], acc[i][j]);
    }
    __syncthreads();
#pragma unroll
    for (int i = 0; i < 4; i++)
#pragma unroll
        for (int j = 0; j < 4; j++) Qs[r0 + i][c0 + j] = acc[i][j];
    __syncthreads();
    if (tid < 64) {
        float mx = -1e30f;
        for (int c = 0; c < 64; c++) mx = fmaxf(mx, Qs[tid][c]);
        float s = 0.f;
        for (int c = 0; c < 64; c++) { float e = __expf(Qs[tid][c] - mx); Qs[tid][c] = e; s += e; }
        float inv = 1.f / s;
        for (int c = 0; c < 64; c++) {
            float v = Qs[tid][c] * inv;
            Qs[tid][c] = v;
            g_K2[bh * 4096 + tid * 64 + c] = v;
        }
    }
    __syncthreads();
    if (tid < 64) {
        float cs = 0.f;
        for (int r = 0; r < 64; r++) cs += Qs[r][tid];
        atomicMax((int*)&g_colmax, __float_as_int(cs));
    }
}

// =====================================================================
// FUSED: S = Ql@K^T -> per-tile softmax stats -> P=exp(S-m_t) -> Tpart=P@V
// =====================================================================
#define AT_QPITCH 72
#define AT_PPITCH 264
#define AT_QH 0
#define AT_QM 9216
#define AT_KH 18432
#define AT_KM 55296
#define AT_PH 0
#define AT_PM 33792
#define AT_RED 92160
#define AT_VH 92160
#define AT_VM 101376
#define AT_SMEM 110592

__global__ __launch_bounds__(256, 2) void attn3_fused() {
    extern __shared__ __align__(128) char sm[];
    uint32_t sb = smem_u32(sm);
    float* s_red = (float*)(sm + AT_RED);
    float* s_rowmax = s_red + 64 * 9;
    int ks = blockIdx.x, bh = blockIdx.y, tid = threadIdx.x;
    int lane = tid & 31, wid = tid >> 5;

    const uint4* qh = (const uint4*)(g_Qlh + bh * 4096);
    const uint4* qm = (const uint4*)(g_Qlm + bh * 4096);
#pragma unroll
    for (int it = 0; it < 2; it++) {
        int c = tid + it * 256;
        int row = c >> 3, col = (c & 7) * 8;
        uint32_t off = (uint32_t)(row * AT_QPITCH + col) * 2;
        *(uint4*)(sm + AT_QH + off) = qh[c];
        *(uint4*)(sm + AT_QM + off) = qm[c];
    }
    const uint4* kh = (const uint4*)(g_Khi + ((size_t)bh * NTOK + ks * 256) * 64);
    const uint4* km = (const uint4*)(g_Kmid + ((size_t)bh * NTOK + ks * 256) * 64);
#pragma unroll
    for (int it = 0; it < 8; it++) {
        int c = tid + it * 256;
        int row = c >> 3, col = (c & 7) * 8;
        uint32_t off = (uint32_t)(row * AT_QPITCH + col) * 2;
        *(uint4*)(sm + AT_KH + off) = kh[c];
        *(uint4*)(sm + AT_KM + off) = km[c];
    }
    __syncthreads();

    int arow = lane & 15;
    int akoff = (lane >> 4) * 8;
    int brow = wid * 32 + (lane & 7) + ((lane >> 4) << 3);
    int bkoff = ((lane >> 3) & 1) * 8;

    float acc[4][4][4] = {};
#pragma unroll
    for (int kk = 0; kk < 64; kk += 16) {
        uint32_t bhi[4][2], bmid[4][2];
#pragma unroll
        for (int np = 0; np < 2; np++) {
            uint32_t off = (uint32_t)((brow + np * 16) * AT_QPITCH + kk + bkoff) * 2;
            uint32_t r0, r1, r2, r3;
            ldsm_x4(r0, r1, r2, r3, sb + AT_KH + off);
            bhi[np * 2][0] = r0; bhi[np * 2][1] = r1;
            bhi[np * 2 + 1][0] = r2; bhi[np * 2 + 1][1] = r3;
            ldsm_x4(r0, r1, r2, r3, sb + AT_KM + off);
            bmid[np * 2][0] = r0; bmid[np * 2][1] = r1;
            bmid[np * 2 + 1][0] = r2; bmid[np * 2 + 1][1] = r3;
        }
#pragma unroll
        for (int mi = 0; mi < 4; mi++) {
            uint32_t ahi[4], amid[4];
            uint32_t off = (uint32_t)((arow + mi * 16) * AT_QPITCH + kk + akoff) * 2;
            ldsm_x4(ahi[0], ahi[1], ahi[2], ahi[3], sb + AT_QH + off);
            ldsm_x4(amid[0], amid[1], amid[2], amid[3], sb + AT_QM + off);
#pragma unroll
            for (int ni = 0; ni < 4; ni++) {
                mma16816(acc[mi][ni], ahi, bhi[ni]);
                mma16816(acc[mi][ni], ahi, bmid[ni]);
                mma16816(acc[mi][ni], amid, bhi[ni]);
            }
        }
    }

#pragma unroll
    for (int mi = 0; mi < 4; mi++)
#pragma unroll
        for (int rr = 0; rr < 2; rr++) {
            float m = -1e30f;
#pragma unroll
            for (int ni = 0; ni < 4; ni++) {
                m = fmaxf(m, acc[mi][ni][rr * 2 + 0]);
                m = fmaxf(m, acc[mi][ni][rr * 2 + 1]);
            }
            m = fmaxf(m, __shfl_xor_sync(~0u, m, 1, 4));
            m = fmaxf(m, __shfl_xor_sync(~0u, m, 2, 4));
            if ((lane & 3) == 0)
                s_red[(mi * 16 + (lane >> 2) + rr * 8) * 9 + wid] = m;
        }
    __syncthreads();
    if (tid < 64) {
        float m = s_red[tid * 9];
#pragma unroll
        for (int w = 1; w < 8; w++) m = fmaxf(m, s_red[tid * 9 + w]);
        s_rowmax[tid] = m;
    }
    __syncthreads();

#pragma unroll
    for (int mi = 0; mi < 4; mi++)
#pragma unroll
        for (int rr = 0; rr < 2; rr++) {
            int row = mi * 16 + (lane >> 2) + rr * 8;
            float m = s_rowmax[row];
            float s = 0.f;
#pragma unroll
            for (int ni = 0; ni < 4; ni++) {
                float p0 = __expf(acc[mi][ni][rr * 2 + 0] - m);
                float p1 = __expf(acc[mi][ni][rr * 2 + 1] - m);
                acc[mi][ni][rr * 2 + 0] = p0;
                acc[mi][ni][rr * 2 + 1] = p1;
                s += p0 + p1;
            }
            s += __shfl_xor_sync(~0u, s, 1, 4);
            s += __shfl_xor_sync(~0u, s, 2, 4);
            if ((lane & 3) == 0) s_red[row * 9 + wid] = s;
        }
    __syncthreads();
    if (tid < 64) {
        float s = 0.f;
#pragma unroll
        for (int w = 0; w < 8; w++) s += s_red[tid * 9 + w];
        g_stats[((size_t)bh * 64 + tid) * KSPLIT + ks] = make_float2(s_rowmax[tid], s);
    }

    __syncthreads();
#pragma unroll
    for (int mi = 0; mi < 4; mi++)
#pragma unroll
        for (int ni = 0; ni < 4; ni++)
#pragma unroll
            for (int rr = 0; rr < 2; rr++) {
                int row = mi * 16 + (lane >> 2) + rr * 8;
                int col = wid * 32 + ni * 8 + 2 * (lane & 3);
                uint32_t off = (uint32_t)(row * AT_PPITCH + col) * 2;
                store_bf16_pair((__nv_bfloat16*)(sm + AT_PH + off),
                                (__nv_bfloat16*)(sm + AT_PM + off),
                                acc[mi][ni][rr * 2 + 0], acc[mi][ni][rr * 2 + 1]);
            }

    int wm = wid >> 2, wn = wid & 3;
    int arow2 = wm * 32 + (lane & 15);
    int bk = lane & 15;
    int bn = wn * 16 + ((lane >> 4) << 3);
    float acc2[2][2][4] = {};

    for (int kq = 0; kq < 4; kq++) {
        size_t gk = (size_t)ks * 256 + kq * 64;
        const uint4* vhp = (const uint4*)(g_Vhi + ((size_t)bh * NTOK + gk) * 64);
        const uint4* vmp = (const uint4*)(g_Vmid + ((size_t)bh * NTOK + gk) * 64);
        __syncthreads();
#pragma unroll
        for (int it = 0; it < 2; it++) {
            int c = tid + it * 256;
            int row = c >> 3, col = (c & 7) * 8;
            uint32_t off = (uint32_t)(row * AT_QPITCH + col) * 2;
            *(uint4*)(sm + AT_VH + off) = vhp[c];
            *(uint4*)(sm + AT_VM + off) = vmp[c];
        }
        __syncthreads();
#pragma unroll
        for (int kk = 0; kk < 64; kk += 16) {
            uint32_t bhi[2][2], bmid[2][2];
            {
                uint32_t off = (uint32_t)((kk + bk) * AT_QPITCH + bn) * 2;
                uint32_t r0, r1, r2, r3;
                ldsm_x4_t(r0, r1, r2, r3, sb + AT_VH + off);
                bhi[0][0] = r0; bhi[0][1] = r1; bhi[1][0] = r2; bhi[1][1] = r3;
                ldsm_x4_t(r0, r1, r2, r3, sb + AT_VM + off);
                bmid[0][0] = r0; bmid[0][1] = r1; bmid[1][0] = r2; bmid[1][1] = r3;
            }
#pragma unroll
            for (int mi = 0; mi < 2; mi++) {
                uint32_t ahi[4], amid[4];
                uint32_t off = (uint32_t)((arow2 + mi * 16) * AT_PPITCH
                                          + kq * 64 + kk + akoff) * 2;
                ldsm_x4(ahi[0], ahi[1], ahi[2], ahi[3], sb + AT_PH + off);
                ldsm_x4(amid[0], amid[1], amid[2], amid[3], sb + AT_PM + off);
#pragma unroll
                for (int ni = 0; ni < 2; ni++) {
                    mma16816(acc2[mi][ni], ahi, bhi[ni]);
                    mma16816(acc2[mi][ni], ahi, bmid[ni]);
                    mma16816(acc2[mi][ni], amid, bhi[ni]);
                }
            }
        }
    }
#pragma unroll
    for (int mi = 0; mi < 2; mi++)
#pragma unroll
        for (int ni = 0; ni < 2; ni++)
#pragma unroll
            for (int rr = 0; rr < 2; rr++) {
                int row = wm * 32 + mi * 16 + (lane >> 2) + rr * 8;
                int col = wn * 16 + ni * 8 + 2 * (lane & 3);
                float2 v;
                v.x = acc2[mi][ni][rr * 2 + 0];
                v.y = acc2[mi][ni][rr * 2 + 1];
                *(float2*)(g_Tpart + (((size_t)ks * BHN + bh) * 64 + row) * 64 + col) = v;
            }
}

// =====================================================================
// Newton-Schulz inverse on TENSOR CORES.  256 threads, 8 warps.
// =====================================================================
#define IM_PITCH 72
#define IM_MAT   18432
#define INV_SMEM (5*IM_MAT)

__device__ __forceinline__ void inv_mm(uint32_t sb, uint32_t oX, uint32_t oY,
                                       float acc[4][4], int lane, int wid) {
    int wm = wid >> 1, wn = wid & 1;
    int arow = wm * 16 + (lane & 15);
    int akoff = (lane >> 4) * 8;
    int bk = lane & 15;
    int bn = wn * 32 + ((lane >> 4) << 3);
#pragma unroll
    for (int kk = 0; kk < 64; kk += 16) {
        uint32_t bhi[4][2], bmid[4][2];
#pragma unroll
        for (int half = 0; half < 2; half++) {
            uint32_t off = (uint32_t)((kk + bk) * IM_PITCH + bn + half * 16) * 2;
            uint32_t r0, r1, r2, r3;
            ldsm_x4_t(r0, r1, r2, r3, sb + oY + off);
            bhi[half * 2][0] = r0; bhi[half * 2][1] = r1;
            bhi[half * 2 + 1][0] = r2; bhi[half * 2 + 1][1] = r3;
            ldsm_x4_t(r0, r1, r2, r3, sb + oY + 9216 + off);
            bmid[half * 2][0] = r0; bmid[half * 2][1] = r1;
            bmid[half * 2 + 1][0] = r2; bmid[half * 2 + 1][1] = r3;
        }
        uint32_t ahi[4], amid[4];
        uint32_t off = (uint32_t)(arow * IM_PITCH + kk + akoff) * 2;
        ldsm_x4(ahi[0], ahi[1], ahi[2], ahi[3], sb + oX + off);
        ldsm_x4(amid[0], amid[1], amid[2], amid[3], sb + oX + 9216 + off);
#pragma unroll
        for (int ni = 0; ni < 4; ni++) {
            mma16816(acc[ni], ahi, bhi[ni]);
            mma16816(acc[ni], ahi, bmid[ni]);
            mma16816(acc[ni], amid, bhi[ni]);
        }
    }
}

__device__ __forceinline__ void inv_store(char* sm, uint32_t oX, uint32_t oZ,
                                          const float acc[4][4],
                                          float alpha, float beta, int lane, int wid) {
    int wm = wid >> 1, wn = wid & 1;
#pragma unroll
    for (int ni = 0; ni < 4; ni++)
#pragma unroll
        for (int rr = 0; rr < 2; rr++) {
            int row = wm * 16 + (lane >> 2) + rr * 8;
            int col = wn * 32 + ni * 8 + 2 * (lane & 3);
            uint32_t off = (uint32_t)(row * IM_PITCH + col) * 2;
            float2 xh = __bfloat1622float2(*(__nv_bfloat162*)(sm + oX + off));
            float2 xm = __bfloat1622float2(*(__nv_bfloat162*)(sm + oX + 9216 + off));
            float z0 = alpha * (xh.x + xm.x) - beta * acc[ni][rr * 2 + 0];
            float z1 = alpha * (xh.y + xm.y) - beta * acc[ni][rr * 2 + 1];
            store_bf16_pair((__nv_bfloat16*)(sm + oZ + off),
                            (__nv_bfloat16*)(sm + oZ + 9216 + off), z0, z1);
        }
}

__global__ __launch_bounds__(256) void inv_kernel() {
    extern __shared__ __align__(128) char sm[];
    __shared__ float sc[64][17];
    __shared__ float sinv[64];
    uint32_t sb = smem_u32(sm);
    int bh = blockIdx.x, tid = threadIdx.x;
    int lane = tid & 31, wid = tid >> 5;
    float ginv = 1.f / g_colmax;

    uint32_t oK = 0, oV = IM_MAT, oA = 2 * IM_MAT, oTa = 3 * IM_MAT, oTb = 4 * IM_MAT;

    if (tid < 64) {
        int row = tid;
        float2 st[KSPLIT];
        float m = -1e30f;
#pragma unroll
        for (int t = 0; t < KSPLIT; t++) {
            st[t] = g_stats[((size_t)bh * 64 + row) * KSPLIT + t];
            m = fmaxf(m, st[t].x);
        }
        float sum = 0.f;
#pragma unroll
        for (int t = 0; t < KSPLIT; t++) {
            float e = __expf(st[t].x - m);
            sc[row][t] = e;
            sum += e * st[t].y;
        }
        sinv[row] = 1.f / sum;
    }
    __syncthreads();

    for (int i = tid * 2; i < 4096; i += 512) {
        int r = i >> 6, c = i & 63;
        uint32_t off = (uint32_t)(r * IM_PITCH + c) * 2;
        float k0 = g_K2[bh * 4096 + r * 64 + c];
        float k1 = g_K2[bh * 4096 + r * 64 + c + 1];
        store_bf16_pair((__nv_bfloat16*)(sm + oK + off),
                        (__nv_bfloat16*)(sm + oK + 9216 + off), k0, k1);
        float v0 = g_K2[bh * 4096 + c * 64 + r] * ginv;
        float v1 = g_K2[bh * 4096 + (c + 1) * 64 + r] * ginv;
        store_bf16_pair((__nv_bfloat16*)(sm + oV + off),
                        (__nv_bfloat16*)(sm + oV + 9216 + off), v0, v1);
    }
    for (int i = tid; i < 4096; i += 256) {
        int r = i >> 6;
        float s = 0.f;
#pragma unroll
        for (int t = 0; t < KSPLIT; t++)
            s = fmaf(g_Tpart[(size_t)t * (BHN * MLAND * HD) + bh * 4096 + i], sc[r][t], s);
        g_W[bh * 4096 + i] = s * sinv[r];
    }

    for (int it = 0; it < 6; it++) {
        __syncthreads();
        {
            float acc[4][4] = {};
            inv_mm(sb, oK, oV, acc, lane, wid);
            inv_store(sm, oK, oA, acc, 0.0f, -1.0f, lane, wid);
        }
        __syncthreads();
        {
            float acc[4][4] = {};
            inv_mm(sb, oA, oA, acc, lane, wid);
            inv_store(sm, oA, oTa, acc, 7.0f, 1.0f, lane, wid);
        }
        __syncthreads();
        {
            float acc[4][4] = {};
            inv_mm(sb, oA, oTa, acc, lane, wid);
            inv_store(sm, oA, oTb, acc, 15.0f, 1.0f, lane, wid);
        }
        __syncthreads();
        {
            float acc[4][4] = {};
            inv_mm(sb, oV, oTb, acc, lane, wid);
            inv_store(sm, oV, oTa, acc, 3.25f, 0.25f, lane, wid);
        }
        uint32_t tmp = oV; oV = oTa; oTa = tmp;
    }
    __syncthreads();

    for (int i = tid * 2; i < 4096; i += 512) {
        int r = i >> 6, c = i & 63;
        uint32_t off = (uint32_t)(r * IM_PITCH + c) * 2;
        float t0 = g_W[bh * 4096 + i];
        float t1 = g_W[bh * 4096 + i + 1];
        store_bf16_pair((__nv_bfloat16*)(sm + oK + off),
                        (__nv_bfloat16*)(sm + oK + 9216 + off), t0, t1);
    }
    __syncthreads();

    {
        float acc[4][4] = {};
        inv_mm(sb, oV, oK, acc, lane, wid);
        int wm = wid >> 1, wn = wid & 1;
#pragma unroll
        for (int ni = 0; ni < 4; ni++)
#pragma unroll
            for (int rr = 0; rr < 2; rr++) {
                int row = wm * 16 + (lane >> 2) + rr * 8;
                int col = wn * 32 + ni * 8 + 2 * (lane & 3);
                size_t idx = (size_t)bh * 4096 + row * 64 + col;
                store_bf16_pair(g_Whi + idx, g_Wmid + idx,
                                acc[ni][rr * 2 + 0], acc[ni][rr * 2 + 1]);
            }
    }
}

// =====================================================================
// Final fused via tensor cores
// =====================================================================
#define FA_PITCH 72
#define FA_QH 0
#define FA_QM (64*FA_PITCH*2)
#define FA_BH (2*64*FA_PITCH*2)
#define FA_BM (3*64*FA_PITCH*2)
#define FA_SS (4*64*FA_PITCH*2)
#define FA_SMEM (FA_SS + 64*68*4)

__global__ __launch_bounds__(256) void final_attn() {
    extern __shared__ __align__(128) char sm[];
    uint32_t sb = smem_u32(sm);
    float* Ss = (float*)(sm + FA_SS);
    int nt = blockIdx.x, bh = blockIdx.y, tid = threadIdx.x;
    int lane = tid & 31, wid = tid >> 5;
    int wm = wid >> 1, wn = wid & 1;
    int b = bh >> 3, h = bh & 7;

    const uint4* qh = (const uint4*)(g_Qhi + (((size_t)bh * NTOK) + nt * 64) * 64);
    const uint4* qm = (const uint4*)(g_Qmid + (((size_t)bh * NTOK) + nt * 64) * 64);
    const uint4* kh = (const uint4*)(g_Klh + bh * 4096);
    const uint4* km = (const uint4*)(g_Klm + bh * 4096);
#pragma unroll
    for (int it = 0; it < 2; it++) {
        int c = tid + it * 256;
        int row = c >> 3, col = (c & 7) * 8;
        uint32_t off = (uint32_t)(row * FA_PITCH + col) * 2;
        *(uint4*)(sm + FA_QH + off) = qh[c];
        *(uint4*)(sm + FA_QM + off) = qm[c];
        *(uint4*)(sm + FA_BH + off) = kh[c];
        *(uint4*)(sm + FA_BM + off) = km[c];
    }
    __syncthreads();

    int arow = wm * 16 + (lane & 15);
    int akoff = (lane >> 4) * 8;
    int brow = wn * 32 + (lane & 7) + ((lane >> 4) << 3);
    int bkoff = ((lane >> 3) & 1) * 8;

    float acc[4][4] = {};
#pragma unroll
    for (int kk = 0; kk < 64; kk += 16) {
        uint32_t bhi[4][2], bmid[4][2];
#pragma unroll
        for (int np = 0; np < 2; np++) {
            uint32_t off = (uint32_t)((brow + np * 16) * FA_PITCH + kk + bkoff) * 2;
            uint32_t r0, r1, r2, r3;
            ldsm_x4(r0, r1, r2, r3, sb + FA_BH + off);
            bhi[np * 2][0] = r0; bhi[np * 2][1] = r1;
            bhi[np * 2 + 1][0] = r2; bhi[np * 2 + 1][1] = r3;
            ldsm_x4(r0, r1, r2, r3, sb + FA_BM + off);
            bmid[np * 2][0] = r0; bmid[np * 2][1] = r1;
            bmid[np * 2 + 1][0] = r2; bmid[np * 2 + 1][1] = r3;
        }
        uint32_t ahi[4], amid[4];
        uint32_t off = (uint32_t)(arow * FA_PITCH + kk + akoff) * 2;
        ldsm_x4(ahi[0], ahi[1], ahi[2], ahi[3], sb + FA_QH + off);
        ldsm_x4(amid[0], amid[1], amid[2], amid[3], sb + FA_QM + off);
#pragma unroll
        for (int ni = 0; ni < 4; ni++) {
            mma16816(acc[ni], ahi, bhi[ni]);
            mma16816(acc[ni], ahi, bmid[ni]);
            mma16816(acc[ni], amid, bhi[ni]);
        }
    }
#pragma unroll
    for (int ni = 0; ni < 4; ni++)
#pragma unroll
        for (int rr = 0; rr < 2; rr++) {
            int row = wm * 16 + (lane >> 2) + rr * 8;
            int col = wn * 32 + ni * 8 + 2 * (lane & 3);
            Ss[row * 68 + col] = acc[ni][rr * 2 + 0];
            Ss[row * 68 + col + 1] = acc[ni][rr * 2 + 1];
        }
    __syncthreads();

    const uint4* wh = (const uint4*)(g_Whi + bh * 4096);
    const uint4* wmv = (const uint4*)(g_Wmid + bh * 4096);
#pragma unroll
    for (int it = 0; it < 2; it++) {
        int c = tid + it * 256;
        int row = c >> 3, col = (c & 7) * 8;
        uint32_t off = (uint32_t)(row * FA_PITCH + col) * 2;
        *(uint4*)(sm + FA_BH + off) = wh[c];
        *(uint4*)(sm + FA_BM + off) = wmv[c];
    }

    {
        int r = tid >> 2;
        int c0 = (tid & 3) * 16;
        float v[16];
        float mx = -1e30f;
#pragma unroll
        for (int j = 0; j < 16; j++) { v[j] = Ss[r * 68 + c0 + j]; mx = fmaxf(mx, v[j]); }
        mx = fmaxf(mx, __shfl_xor_sync(~0u, mx, 1, 4));
        mx = fmaxf(mx, __shfl_xor_sync(~0u, mx, 2, 4));
        float s = 0.f;
#pragma unroll
        for (int j = 0; j < 16; j++) { v[j] = __expf(v[j] - mx); s += v[j]; }
        s += __shfl_xor_sync(~0u, s, 1, 4);
        s += __shfl_xor_sync(~0u, s, 2, 4);
        float inv = 1.f / s;
#pragma unroll
        for (int j = 0; j < 16; j += 2) {
            float p0 = v[j] * inv, p1 = v[j + 1] * inv;
            uint32_t off = (uint32_t)(r * FA_PITCH + c0 + j) * 2;
            store_bf16_pair((__nv_bfloat16*)(sm + FA_QH + off),
                            (__nv_bfloat16*)(sm + FA_QM + off), p0, p1);
        }
    }
    __syncthreads();

    int bk = lane & 15;
    int bn = wn * 32 + ((lane >> 4) << 3);
    float acc2[4][4] = {};
#pragma unroll
    for (int kk = 0; kk < 64; kk += 16) {
        uint32_t bhi[4][2], bmid[4][2];
#pragma unroll
        for (int half = 0; half < 2; half++) {
            uint32_t off = (uint32_t)((kk + bk) * FA_PITCH + bn + half * 16) * 2;
            uint32_t r0, r1, r2, r3;
            ldsm_x4_t(r0, r1, r2, r3, sb + FA_BH + off);
            bhi[half * 2][0] = r0; bhi[half * 2][1] = r1;
            bhi[half * 2 + 1][0] = r2; bhi[half * 2 + 1][1] = r3;
            ldsm_x4_t(r0, r1, r2, r3, sb + FA_BM + off);
            bmid[half * 2][0] = r0; bmid[half * 2][1] = r1;
            bmid[half * 2 + 1][0] = r2; bmid[half * 2 + 1][1] = r3;
        }
        uint32_t ahi[4], amid[4];
        uint32_t off = (uint32_t)(arow * FA_PITCH + kk + akoff) * 2;
        ldsm_x4(ahi[0], ahi[1], ahi[2], ahi[3], sb + FA_QH + off);
        ldsm_x4(amid[0], amid[1], amid[2], amid[3], sb + FA_QM + off);
#pragma unroll
        for (int ni = 0; ni < 4; ni++) {
            mma16816(acc2[ni], ahi, bhi[ni]);
            mma16816(acc2[ni], ahi, bmid[ni]);
            mma16816(acc2[ni], amid, bhi[ni]);
        }
    }
#pragma unroll
    for (int ni = 0; ni < 4; ni++)
#pragma unroll
        for (int rr = 0; rr < 2; rr++) {
            int row = wm * 16 + (lane >> 2) + rr * 8;
            int col = wn * 32 + ni * 8 + 2 * (lane & 3);
            size_t idx = (((size_t)b * NTOK) + nt * 64 + row) * CDIM + h * 64 + col;
            store_bf16_pair(g_Xhi + idx, g_Xmid + idx,
                            acc2[ni][rr * 2 + 0], acc2[ni][rr * 2 + 1]);
        }
}

// =====================================================================
// host launcher: concurrent-stream head pipelining; round-14 tail
// =====================================================================
extern "C" void kernel_launch(void* const* d_in, const int* in_sizes, int n_in,
                              void* d_out, int out_size) {
    const float* x      = (const float*)d_in[0];
    const float* qkv_w  = (const float*)d_in[1];
    const float* proj_w = (const float*)d_in[2];
    const float* proj_b = (const float*)d_in[3];
    float* out = (float*)d_out;

    static cudaStream_t s2 = nullptr;
    static cudaEvent_t ev1 = nullptr, evW = nullptr, evG1 = nullptr,
                       ev3 = nullptr, ev4 = nullptr;
    if (s2 == nullptr) {
        cudaStreamCreateWithFlags(&s2, cudaStreamNonBlocking);
        cudaEventCreateWithFlags(&ev1, cudaEventDisableTiming);
        cudaEventCreateWithFlags(&evW, cudaEventDisableTiming);
        cudaEventCreateWithFlags(&evG1, cudaEventDisableTiming);
        cudaEventCreateWithFlags(&ev3, cudaEventDisableTiming);
        cudaEventCreateWithFlags(&ev4, cudaEventDisableTiming);
    }

    __nv_bfloat16 *xhi, *xmid, *whi, *wmid, *phi, *pmid, *Xhi, *Xmid;
    cudaGetSymbolAddress((void**)&xhi,  g_xhi);
    cudaGetSymbolAddress((void**)&xmid, g_xmid);
    cudaGetSymbolAddress((void**)&whi,  g_whi);
    cudaGetSymbolAddress((void**)&wmid, g_wmid);
    cudaGetSymbolAddress((void**)&phi,  g_phi);
    cudaGetSymbolAddress((void**)&pmid, g_pmid);
    cudaGetSymbolAddress((void**)&Xhi,  g_Xhi);
    cudaGetSymbolAddress((void**)&Xmid, g_Xmid);

    cudaFuncSetAttribute(hmma_gemm<0>, cudaFuncAttributeMaxDynamicSharedMemorySize, GEMM_SMEM);
    cudaFuncSetAttribute(hmma_gemm<1>, cudaFuncAttributeMaxDynamicSharedMemorySize, GEMM_SMEM);
    cudaFuncSetAttribute(attn3_fused, cudaFuncAttributeMaxDynamicSharedMemorySize, AT_SMEM);
    cudaFuncSetAttribute(final_attn, cudaFuncAttributeMaxDynamicSharedMemorySize, FA_SMEM);
    cudaFuncSetAttribute(inv_kernel, cudaFuncAttributeMaxDynamicSharedMemorySize, INV_SMEM);

    const int XH_N4 = 8192 * 512 / 4;
    const size_t XH_ELEM = (size_t)8192 * 512;

    // ---- head: both GEMM halves run CONCURRENTLY on different streams ----
    cudaEventRecord(ev1, 0);
    cudaStreamWaitEvent(s2, ev1, 0);
    // s2: weights, then x half1, then GEMM half1 (all deps local to s2)
    split_kernel<<<768, 256, 0, s2>>>(qkv_w, whi, wmid, 1536 * 512 / 4);
    split_kernel<<<256, 256, 0, s2>>>(proj_w, phi, pmid, 512 * 512 / 4);
    cudaEventRecord(evW, s2);
    split_kernel<<<4096, 256, 0, s2>>>(x + XH_ELEM, xhi + XH_ELEM, xmid + XH_ELEM, XH_N4);
    hmma_gemm<0><<<dim3(12, 64), 256, GEMM_SMEM, s2>>>(xhi, xmid, whi, wmid,
                                                       nullptr, nullptr, 64);
    cudaEventRecord(evG1, s2);
    // main: x half0, then GEMM half0 (waits weights from s2)
    split_kernel<<<4096, 256>>>(x, xhi, xmid, XH_N4);
    cudaStreamWaitEvent(0, evW, 0);
    hmma_gemm<0><<<dim3(12, 64), 256, GEMM_SMEM>>>(xhi, xmid, whi, wmid,
                                                   nullptr, nullptr, 0);
    cudaStreamWaitEvent(0, evG1, 0);

    pool_kernel<<<BHN * MLAND, 64>>>();

    // ---- middle: k2 (s2) || attn3 (main) ----
    cudaEventRecord(ev3, 0);
    cudaStreamWaitEvent(s2, ev3, 0);
    k2_kernel<<<BHN, 256, 0, s2>>>();
    attn3_fused<<<dim3(KSPLIT, BHN), 256, AT_SMEM>>>();
    cudaEventRecord(ev4, s2);
    cudaStreamWaitEvent(0, ev4, 0);

    // ---- tail: round-14 (unsplit) ----
    inv_kernel<<<BHN, 256, INV_SMEM>>>();
    final_attn<<<dim3(64, BHN), 256, FA_SMEM>>>();
    hmma_gemm<1><<<dim3(4, 128), 256, GEMM_SMEM>>>(Xhi, Xmid, phi, pmid, proj_b, out, 0);
}

// round 17
// speedup vs baseline: 1.0709x; 1.0095x over previous
#include <cuda_runtime.h>
#include <cuda_bf16.h>
#include <math.h>
#include <stdint.h>

// ---------------- problem constants ----------------
#define NBATCH 4
#define NHEAD  8
#define BHN    (NBATCH*NHEAD)      // 32
#define NTOK   4096
#define CDIM   512
#define HD     64
#define MLAND  64
#define KSPLIT 16
#define SCALE  0.35355339059327373f   // 64^-0.25

// ---------------- device scratch ----------------
__device__ float g_Ql[BHN*MLAND*HD];
__device__ float g_Kl[BHN*MLAND*HD];
__device__ float g_K2[BHN*MLAND*MLAND];
__device__ float g_W [BHN*MLAND*HD];
__device__ float g_Tpart[KSPLIT*BHN*MLAND*HD];
__device__ float2 g_stats[BHN*MLAND*KSPLIT];
__device__ float g_colmax;

// bf16 hi/mid split buffers
__device__ __nv_bfloat16 g_xhi [16384*512];
__device__ __nv_bfloat16 g_xmid[16384*512];
__device__ __nv_bfloat16 g_whi [1536*512];
__device__ __nv_bfloat16 g_wmid[1536*512];
__device__ __nv_bfloat16 g_phi [512*512];
__device__ __nv_bfloat16 g_pmid[512*512];
__device__ __nv_bfloat16 g_Xhi [16384*512];
__device__ __nv_bfloat16 g_Xmid[16384*512];
__device__ __nv_bfloat16 g_Qhi [BHN*NTOK*HD];
__device__ __nv_bfloat16 g_Qmid[BHN*NTOK*HD];
__device__ __nv_bfloat16 g_Khi [BHN*NTOK*HD];
__device__ __nv_bfloat16 g_Kmid[BHN*NTOK*HD];
__device__ __nv_bfloat16 g_Vhi [BHN*NTOK*HD];
__device__ __nv_bfloat16 g_Vmid[BHN*NTOK*HD];
__device__ __nv_bfloat16 g_Qlh [BHN*MLAND*HD];
__device__ __nv_bfloat16 g_Qlm [BHN*MLAND*HD];
__device__ __nv_bfloat16 g_Klh [BHN*MLAND*HD];
__device__ __nv_bfloat16 g_Klm [BHN*MLAND*HD];
__device__ __nv_bfloat16 g_Whi [BHN*MLAND*HD];
__device__ __nv_bfloat16 g_Wmid[BHN*MLAND*HD];

// ==================== PTX helpers ====================
__device__ __forceinline__ uint32_t smem_u32(const void* p) {
    uint32_t a;
    asm("{ .reg .u64 t; cvta.to.shared.u64 t, %1; cvt.u32.u64 %0, t; }" : "=r"(a) : "l"(p));
    return a;
}
__device__ __forceinline__ void ldsm_x4(uint32_t& r0, uint32_t& r1, uint32_t& r2, uint32_t& r3,
                                        uint32_t addr) {
    asm volatile("ldmatrix.sync.aligned.m8n8.x4.shared.b16 {%0,%1,%2,%3}, [%4];"
                 : "=r"(r0), "=r"(r1), "=r"(r2), "=r"(r3) : "r"(addr));
}
__device__ __forceinline__ void ldsm_x4_t(uint32_t& r0, uint32_t& r1, uint32_t& r2, uint32_t& r3,
                                          uint32_t addr) {
    asm volatile("ldmatrix.sync.aligned.m8n8.x4.trans.shared.b16 {%0,%1,%2,%3}, [%4];"
                 : "=r"(r0), "=r"(r1), "=r"(r2), "=r"(r3) : "r"(addr));
}
__device__ __forceinline__ void mma16816(float* c, const uint32_t* a, const uint32_t* b) {
    asm volatile("mma.sync.aligned.m16n8k16.row.col.f32.bf16.bf16.f32 "
                 "{%0,%1,%2,%3}, {%4,%5,%6,%7}, {%8,%9}, {%0,%1,%2,%3};"
                 : "+f"(c[0]), "+f"(c[1]), "+f"(c[2]), "+f"(c[3])
                 : "r"(a[0]), "r"(a[1]), "r"(a[2]), "r"(a[3]), "r"(b[0]), "r"(b[1]));
}
#define CP_ASYNC(dst, src) asm volatile("cp.async.cg.shared.global [%0], [%1], 16;" :: "r"(dst), "l"(src))
#define CP_COMMIT()        asm volatile("cp.async.commit_group;" ::: "memory")
#define CP_WAIT1()         asm volatile("cp.async.wait_group 1;" ::: "memory")
#define CP_WAIT0()         asm volatile("cp.async.wait_group 0;" ::: "memory")

__device__ __forceinline__ void store_bf16_pair(__nv_bfloat16* hi, __nv_bfloat16* mid,
                                                float x, float y) {
    __nv_bfloat16 h0 = __float2bfloat16(x);
    __nv_bfloat16 h1 = __float2bfloat16(y);
    *(__nv_bfloat162*)hi = __nv_bfloat162(h0, h1);
    *(__nv_bfloat162*)mid = __nv_bfloat162(__float2bfloat16(x - __bfloat162float(h0)),
                                           __float2bfloat16(y - __bfloat162float(h1)));
}

// ==================== bf16 3x-split HMMA GEMM (big GEMMs) ====================
// y_eff = ya + blockIdx.y + (blockIdx.y>>4)*yb   (row-half pipelining)
#define PITCH 40
#define MAT_BYTES (128*PITCH*2)
#define SM_A_HI  0
#define SM_A_MID (1*MAT_BYTES)
#define SM_B_HI  (2*MAT_BYTES)
#define SM_B_MID (3*MAT_BYTES)
#define BUF_BYTES (4*MAT_BYTES)
#define GEMM_SMEM (2*BUF_BYTES)

__device__ __forceinline__ void load_stage(uint32_t bufb, int k0, size_t rowA0, size_t rowB0,
                                           const __nv_bfloat16* __restrict__ Ahi,
                                           const __nv_bfloat16* __restrict__ Amid,
                                           const __nv_bfloat16* __restrict__ Bhi,
                                           const __nv_bfloat16* __restrict__ Bmid,
                                           int tid) {
#pragma unroll
    for (int half = 0; half < 2; half++) {
        int c = tid + half * 256;
        int r = c >> 2, cc = (c & 3) * 8;
        uint32_t d = bufb + (uint32_t)(r * PITCH + cc) * 2;
        size_t goffA = (rowA0 + r) * 512 + k0 + cc;
        size_t goffB = (rowB0 + r) * 512 + k0 + cc;
        CP_ASYNC(d + SM_A_HI,  Ahi  + goffA);
        CP_ASYNC(d + SM_A_MID, Amid + goffA);
        CP_ASYNC(d + SM_B_HI,  Bhi  + goffB);
        CP_ASYNC(d + SM_B_MID, Bmid + goffB);
    }
    CP_COMMIT();
}

template<int MODE>
__global__ __launch_bounds__(256, 2) void hmma_gemm(
    const __nv_bfloat16* __restrict__ Ahi, const __nv_bfloat16* __restrict__ Amid,
    const __nv_bfloat16* __restrict__ Bhi, const __nv_bfloat16* __restrict__ Bmid,
    const float* __restrict__ bias, float* __restrict__ Cout, int ya, int yb)
{
    extern __shared__ __align__(128) char sm[];
    uint32_t sb = smem_u32(sm);
    int tid = threadIdx.x;
    int lane = tid & 31, wid = tid >> 5;
    int wm = wid >> 2, wn = wid & 3;
    int y_eff = ya + blockIdx.y + ((blockIdx.y >> 4) * yb);
    size_t rowA0 = (size_t)y_eff * 128;
    size_t rowB0 = (size_t)blockIdx.x * 128;

    float acc[4][4][4] = {};

    int arow  = wm * 64 + (lane & 15);
    int akoff = (lane >> 4) * 8;
    int brow  = wn * 32 + (lane & 7) + ((lane >> 4) << 3);
    int bkoff = ((lane >> 3) & 1) * 8;

    load_stage(sb, 0, rowA0, rowB0, Ahi, Amid, Bhi, Bmid, tid);

    for (int t = 0; t < 16; t++) {
        if (t + 1 < 16) {
            load_stage(sb + ((t + 1) & 1) * BUF_BYTES, (t + 1) * 32, rowA0, rowB0,
                       Ahi, Amid, Bhi, Bmid, tid);
            CP_WAIT1();
        } else {
            CP_WAIT0();
        }
        __syncthreads();

        uint32_t base = sb + (t & 1) * BUF_BYTES;
#pragma unroll
        for (int kk = 0; kk < 32; kk += 16) {
            uint32_t bhi[4][2], bmid[4][2];
#pragma unroll
            for (int np = 0; np < 2; np++) {
                uint32_t off = (uint32_t)((brow + np * 16) * PITCH + kk + bkoff) * 2;
                uint32_t r0, r1, r2, r3;
                ldsm_x4(r0, r1, r2, r3, base + SM_B_HI + off);
                bhi[np * 2][0] = r0; bhi[np * 2][1] = r1;
                bhi[np * 2 + 1][0] = r2; bhi[np * 2 + 1][1] = r3;
                ldsm_x4(r0, r1, r2, r3, base + SM_B_MID + off);
                bmid[np * 2][0] = r0; bmid[np * 2][1] = r1;
                bmid[np * 2 + 1][0] = r2; bmid[np * 2 + 1][1] = r3;
            }
#pragma unroll
            for (int mi = 0; mi < 4; mi++) {
                uint32_t ahi[4], amid[4];
                uint32_t off = (uint32_t)((arow + mi * 16) * PITCH + kk + akoff) * 2;
                ldsm_x4(ahi[0], ahi[1], ahi[2], ahi[3], base + SM_A_HI + off);
                ldsm_x4(amid[0], amid[1], amid[2], amid[3], base + SM_A_MID + off);
#pragma unroll
                for (int ni = 0; ni < 4; ni++) {
                    mma16816(acc[mi][ni], ahi, bhi[ni]);
                    mma16816(acc[mi][ni], ahi, bmid[ni]);
                    mma16816(acc[mi][ni], amid, bhi[ni]);
                }
            }
        }
        __syncthreads();
    }

    int colW = blockIdx.x * 128 + wn * 32 + 2 * (lane & 3);
    int rowW = y_eff * 128 + wm * 64 + (lane >> 2);
#pragma unroll
    for (int ni = 0; ni < 4; ni++) {
        int col = colW + ni * 8;
#pragma unroll
        for (int mi = 0; mi < 4; mi++) {
            int row0 = rowW + mi * 16;
            if (MODE == 0) {
                int which = col >> 9;
                int h = (col >> 6) & 7;
                int d = col & 63;
#pragma unroll
                for (int rr = 0; rr < 2; rr++) {
                    int row = row0 + rr * 8;
                    int b = row >> 12, n = row & 4095;
                    size_t idx = ((size_t)(b * 8 + h) * NTOK + n) * HD + d;
                    float vx = acc[mi][ni][rr * 2 + 0];
                    float vy = acc[mi][ni][rr * 2 + 1];
                    if (which == 0) {
                        store_bf16_pair(g_Qhi + idx, g_Qmid + idx, vx * SCALE, vy * SCALE);
                    } else if (which == 1) {
                        store_bf16_pair(g_Khi + idx, g_Kmid + idx, vx * SCALE, vy * SCALE);
                    } else {
                        store_bf16_pair(g_Vhi + idx, g_Vmid + idx, vx, vy);
                    }
                }
            } else {
                float2 bb = *(const float2*)(bias + col);
#pragma unroll
                for (int rr = 0; rr < 2; rr++) {
                    int row = row0 + rr * 8;
                    float2 v;
                    v.x = acc[mi][ni][rr * 2 + 0] + bb.x;
                    v.y = acc[mi][ni][rr * 2 + 1] + bb.y;
                    *(float2*)(Cout + (size_t)row * 512 + col) = v;
                }
            }
        }
    }
}

// ==================== fp32 -> bf16 hi/mid split ====================
__global__ void split_kernel(const float* __restrict__ src,
                             __nv_bfloat16* __restrict__ hi,
                             __nv_bfloat16* __restrict__ mid, int n4) {
    int i = blockIdx.x * 256 + threadIdx.x;
    if (i >= n4) return;
    float4 v = ((const float4*)src)[i];
    store_bf16_pair(hi + i * 4,     mid + i * 4,     v.x, v.y);
    store_bf16_pair(hi + i * 4 + 2, mid + i * 4 + 2, v.z, v.w);
}

// =====================================================================
// Landmark pooling (coalesced)
// =====================================================================
__device__ __forceinline__ void acc8(float* s, uint4 v) {
    const __nv_bfloat162* p = (const __nv_bfloat162*)&v;
#pragma unroll
    for (int j = 0; j < 4; j++) {
        float2 f = __bfloat1622float2(p[j]);
        s[j * 2 + 0] += f.x;
        s[j * 2 + 1] += f.y;
    }
}

__global__ void pool_kernel() {
    __shared__ float smq[8][64];
    __shared__ float smk[8][64];
    if (blockIdx.x == 0 && threadIdx.x == 0) g_colmax = 0.0f;
    int bm = blockIdx.x;
    int bh = bm >> 6, m = bm & 63;
    int tid = threadIdx.x;
    int grp = tid >> 3, ch = tid & 7;
    size_t rowbase = ((size_t)bh * NTOK + m * 64) * HD;
    float sq[8] = {}, sk[8] = {};
#pragma unroll
    for (int tt = 0; tt < 8; tt++) {
        size_t off = rowbase + (size_t)(grp * 8 + tt) * HD + ch * 8;
        acc8(sq, *(const uint4*)(g_Qhi + off));
        acc8(sq, *(const uint4*)(g_Qmid + off));
        acc8(sk, *(const uint4*)(g_Khi + off));
        acc8(sk, *(const uint4*)(g_Kmid + off));
    }
#pragma unroll
    for (int j = 0; j < 8; j++) {
        smq[grp][ch * 8 + j] = sq[j];
        smk[grp][ch * 8 + j] = sk[j];
    }
    __syncthreads();
    int d = tid;
    float q = 0.f, k = 0.f;
#pragma unroll
    for (int g = 0; g < 8; g++) { q += smq[g][d]; k += smk[g][d]; }
    float ql = q * (1.f / 64.f);
    float kl = k * (1.f / 64.f);
    int idx = (bh * 64 + m) * 64 + d;
    g_Ql[idx] = ql;
    g_Kl[idx] = kl;
    __nv_bfloat16 hq = __float2bfloat16(ql);
    g_Qlh[idx] = hq;
    g_Qlm[idx] = __float2bfloat16(ql - __bfloat162float(hq));
    __nv_bfloat16 hk = __float2bfloat16(kl);
    g_Klh[idx] = hk;
    g_Klm[idx] = __float2bfloat16(kl - __bfloat162float(hk));
}

// =====================================================================
// kernel_2 = softmax(Ql @ Kl^T) + colsum max
// =====================================================================
__global__ __launch_bounds__(256) void k2_kernel() {
    __shared__ float Qs[64][68];
    __shared__ float Ks[64][68];
    int bh = blockIdx.x, tid = threadIdx.x;
    for (int i = tid; i < 4096; i += 256) {
        Qs[i >> 6][i & 63] = g_Ql[bh * 4096 + i];
        Ks[i >> 6][i & 63] = g_Kl[bh * 4096 + i];
    }
    __syncthreads();
    int ty = tid >> 4, tx = tid & 15, r0 = ty * 4, c0 = tx * 4;
    float acc[4][4] = {};
    for (int k = 0; k < 64; k++) {
        float a[4], b[4];
#pragma unroll
        for (int i = 0; i < 4; i++) a[i] = Qs[r0 + i][k];
#pragma unroll
        for (int j = 0; j < 4; j++) b[j] = Ks[c0 + j][k];
#pragma unroll
        for (int i = 0; i < 4; i++)
#pragma unroll
            for (int j = 0; j < 4; j++) acc[i][j] = fmaf(a[i], b[j], acc[i][j]);
    }
    __syncthreads();
#pragma unroll
    for (int i = 0; i < 4; i++)
#pragma unroll
        for (int j = 0; j < 4; j++) Qs[r0 + i][c0 + j] = acc[i][j];
    __syncthreads();
    if (tid < 64) {
        float mx = -1e30f;
        for (int c = 0; c < 64; c++) mx = fmaxf(mx, Qs[tid][c]);
        float s = 0.f;
        for (int c = 0; c < 64; c++) { float e = __expf(Qs[tid][c] - mx); Qs[tid][c] = e; s += e; }
        float inv = 1.f / s;
        for (int c = 0; c < 64; c++) {
            float v = Qs[tid][c] * inv;
            Qs[tid][c] = v;
            g_K2[bh * 4096 + tid * 64 + c] = v;
        }
    }
    __syncthreads();
    if (tid < 64) {
        float cs = 0.f;
        for (int r = 0; r < 64; r++) cs += Qs[r][tid];
        atomicMax((int*)&g_colmax, __float_as_int(cs));
    }
}

// =====================================================================
// FUSED: S = Ql@K^T -> per-tile softmax stats -> P=exp(S-m_t) -> Tpart=P@V
// =====================================================================
#define AT_QPITCH 72
#define AT_PPITCH 264
#define AT_QH 0
#define AT_QM 9216
#define AT_KH 18432
#define AT_KM 55296
#define AT_PH 0
#define AT_PM 33792
#define AT_RED 92160
#define AT_VH 92160
#define AT_VM 101376
#define AT_SMEM 110592

__global__ __launch_bounds__(256, 2) void attn3_fused() {
    extern __shared__ __align__(128) char sm[];
    uint32_t sb = smem_u32(sm);
    float* s_red = (float*)(sm + AT_RED);
    float* s_rowmax = s_red + 64 * 9;
    int ks = blockIdx.x, bh = blockIdx.y, tid = threadIdx.x;
    int lane = tid & 31, wid = tid >> 5;

    const uint4* qh = (const uint4*)(g_Qlh + bh * 4096);
    const uint4* qm = (const uint4*)(g_Qlm + bh * 4096);
#pragma unroll
    for (int it = 0; it < 2; it++) {
        int c = tid + it * 256;
        int row = c >> 3, col = (c & 7) * 8;
        uint32_t off = (uint32_t)(row * AT_QPITCH + col) * 2;
        *(uint4*)(sm + AT_QH + off) = qh[c];
        *(uint4*)(sm + AT_QM + off) = qm[c];
    }
    const uint4* kh = (const uint4*)(g_Khi + ((size_t)bh * NTOK + ks * 256) * 64);
    const uint4* km = (const uint4*)(g_Kmid + ((size_t)bh * NTOK + ks * 256) * 64);
#pragma unroll
    for (int it = 0; it < 8; it++) {
        int c = tid + it * 256;
        int row = c >> 3, col = (c & 7) * 8;
        uint32_t off = (uint32_t)(row * AT_QPITCH + col) * 2;
        *(uint4*)(sm + AT_KH + off) = kh[c];
        *(uint4*)(sm + AT_KM + off) = km[c];
    }
    __syncthreads();

    int arow = lane & 15;
    int akoff = (lane >> 4) * 8;
    int brow = wid * 32 + (lane & 7) + ((lane >> 4) << 3);
    int bkoff = ((lane >> 3) & 1) * 8;

    float acc[4][4][4] = {};
#pragma unroll
    for (int kk = 0; kk < 64; kk += 16) {
        uint32_t bhi[4][2], bmid[4][2];
#pragma unroll
        for (int np = 0; np < 2; np++) {
            uint32_t off = (uint32_t)((brow + np * 16) * AT_QPITCH + kk + bkoff) * 2;
            uint32_t r0, r1, r2, r3;
            ldsm_x4(r0, r1, r2, r3, sb + AT_KH + off);
            bhi[np * 2][0] = r0; bhi[np * 2][1] = r1;
            bhi[np * 2 + 1][0] = r2; bhi[np * 2 + 1][1] = r3;
            ldsm_x4(r0, r1, r2, r3, sb + AT_KM + off);
            bmid[np * 2][0] = r0; bmid[np * 2][1] = r1;
            bmid[np * 2 + 1][0] = r2; bmid[np * 2 + 1][1] = r3;
        }
#pragma unroll
        for (int mi = 0; mi < 4; mi++) {
            uint32_t ahi[4], amid[4];
            uint32_t off = (uint32_t)((arow + mi * 16) * AT_QPITCH + kk + akoff) * 2;
            ldsm_x4(ahi[0], ahi[1], ahi[2], ahi[3], sb + AT_QH + off);
            ldsm_x4(amid[0], amid[1], amid[2], amid[3], sb + AT_QM + off);
#pragma unroll
            for (int ni = 0; ni < 4; ni++) {
                mma16816(acc[mi][ni], ahi, bhi[ni]);
                mma16816(acc[mi][ni], ahi, bmid[ni]);
                mma16816(acc[mi][ni], amid, bhi[ni]);
            }
        }
    }

#pragma unroll
    for (int mi = 0; mi < 4; mi++)
#pragma unroll
        for (int rr = 0; rr < 2; rr++) {
            float m = -1e30f;
#pragma unroll
            for (int ni = 0; ni < 4; ni++) {
                m = fmaxf(m, acc[mi][ni][rr * 2 + 0]);
                m = fmaxf(m, acc[mi][ni][rr * 2 + 1]);
            }
            m = fmaxf(m, __shfl_xor_sync(~0u, m, 1, 4));
            m = fmaxf(m, __shfl_xor_sync(~0u, m, 2, 4));
            if ((lane & 3) == 0)
                s_red[(mi * 16 + (lane >> 2) + rr * 8) * 9 + wid] = m;
        }
    __syncthreads();
    if (tid < 64) {
        float m = s_red[tid * 9];
#pragma unroll
        for (int w = 1; w < 8; w++) m = fmaxf(m, s_red[tid * 9 + w]);
        s_rowmax[tid] = m;
    }
    __syncthreads();

#pragma unroll
    for (int mi = 0; mi < 4; mi++)
#pragma unroll
        for (int rr = 0; rr < 2; rr++) {
            int row = mi * 16 + (lane >> 2) + rr * 8;
            float m = s_rowmax[row];
            float s = 0.f;
#pragma unroll
            for (int ni = 0; ni < 4; ni++) {
                float p0 = __expf(acc[mi][ni][rr * 2 + 0] - m);
                float p1 = __expf(acc[mi][ni][rr * 2 + 1] - m);
                acc[mi][ni][rr * 2 + 0] = p0;
                acc[mi][ni][rr * 2 + 1] = p1;
                s += p0 + p1;
            }
            s += __shfl_xor_sync(~0u, s, 1, 4);
            s += __shfl_xor_sync(~0u, s, 2, 4);
            if ((lane & 3) == 0) s_red[row * 9 + wid] = s;
        }
    __syncthreads();
    if (tid < 64) {
        float s = 0.f;
#pragma unroll
        for (int w = 0; w < 8; w++) s += s_red[tid * 9 + w];
        g_stats[((size_t)bh * 64 + tid) * KSPLIT + ks] = make_float2(s_rowmax[tid], s);
    }

    __syncthreads();
#pragma unroll
    for (int mi = 0; mi < 4; mi++)
#pragma unroll
        for (int ni = 0; ni < 4; ni++)
#pragma unroll
            for (int rr = 0; rr < 2; rr++) {
                int row = mi * 16 + (lane >> 2) + rr * 8;
                int col = wid * 32 + ni * 8 + 2 * (lane & 3);
                uint32_t off = (uint32_t)(row * AT_PPITCH + col) * 2;
                store_bf16_pair((__nv_bfloat16*)(sm + AT_PH + off),
                                (__nv_bfloat16*)(sm + AT_PM + off),
                                acc[mi][ni][rr * 2 + 0], acc[mi][ni][rr * 2 + 1]);
            }

    int wm = wid >> 2, wn = wid & 3;
    int arow2 = wm * 32 + (lane & 15);
    int bk = lane & 15;
    int bn = wn * 16 + ((lane >> 4) << 3);
    float acc2[2][2][4] = {};

    for (int kq = 0; kq < 4; kq++) {
        size_t gk = (size_t)ks * 256 + kq * 64;
        const uint4* vhp = (const uint4*)(g_Vhi + ((size_t)bh * NTOK + gk) * 64);
        const uint4* vmp = (const uint4*)(g_Vmid + ((size_t)bh * NTOK + gk) * 64);
        __syncthreads();
#pragma unroll
        for (int it = 0; it < 2; it++) {
            int c = tid + it * 256;
            int row = c >> 3, col = (c & 7) * 8;
            uint32_t off = (uint32_t)(row * AT_QPITCH + col) * 2;
            *(uint4*)(sm + AT_VH + off) = vhp[c];
            *(uint4*)(sm + AT_VM + off) = vmp[c];
        }
        __syncthreads();
#pragma unroll
        for (int kk = 0; kk < 64; kk += 16) {
            uint32_t bhi[2][2], bmid[2][2];
            {
                uint32_t off = (uint32_t)((kk + bk) * AT_QPITCH + bn) * 2;
                uint32_t r0, r1, r2, r3;
                ldsm_x4_t(r0, r1, r2, r3, sb + AT_VH + off);
                bhi[0][0] = r0; bhi[0][1] = r1; bhi[1][0] = r2; bhi[1][1] = r3;
                ldsm_x4_t(r0, r1, r2, r3, sb + AT_VM + off);
                bmid[0][0] = r0; bmid[0][1] = r1; bmid[1][0] = r2; bmid[1][1] = r3;
            }
#pragma unroll
            for (int mi = 0; mi < 2; mi++) {
                uint32_t ahi[4], amid[4];
                uint32_t off = (uint32_t)((arow2 + mi * 16) * AT_PPITCH
                                          + kq * 64 + kk + akoff) * 2;
                ldsm_x4(ahi[0], ahi[1], ahi[2], ahi[3], sb + AT_PH + off);
                ldsm_x4(amid[0], amid[1], amid[2], amid[3], sb + AT_PM + off);
#pragma unroll
                for (int ni = 0; ni < 2; ni++) {
                    mma16816(acc2[mi][ni], ahi, bhi[ni]);
                    mma16816(acc2[mi][ni], ahi, bmid[ni]);
                    mma16816(acc2[mi][ni], amid, bhi[ni]);
                }
            }
        }
    }
#pragma unroll
    for (int mi = 0; mi < 2; mi++)
#pragma unroll
        for (int ni = 0; ni < 2; ni++)
#pragma unroll
            for (int rr = 0; rr < 2; rr++) {
                int row = wm * 32 + mi * 16 + (lane >> 2) + rr * 8;
                int col = wn * 16 + ni * 8 + 2 * (lane & 3);
                float2 v;
                v.x = acc2[mi][ni][rr * 2 + 0];
                v.y = acc2[mi][ni][rr * 2 + 1];
                *(float2*)(g_Tpart + (((size_t)ks * BHN + bh) * 64 + row) * 64 + col) = v;
            }
}

// =====================================================================
// Newton-Schulz inverse on TENSOR CORES.  256 threads, 8 warps.
// =====================================================================
#define IM_PITCH 72
#define IM_MAT   18432
#define INV_SMEM (5*IM_MAT)

__device__ __forceinline__ void inv_mm(uint32_t sb, uint32_t oX, uint32_t oY,
                                       float acc[4][4], int lane, int wid) {
    int wm = wid >> 1, wn = wid & 1;
    int arow = wm * 16 + (lane & 15);
    int akoff = (lane >> 4) * 8;
    int bk = lane & 15;
    int bn = wn * 32 + ((lane >> 4) << 3);
#pragma unroll
    for (int kk = 0; kk < 64; kk += 16) {
        uint32_t bhi[4][2], bmid[4][2];
#pragma unroll
        for (int half = 0; half < 2; half++) {
            uint32_t off = (uint32_t)((kk + bk) * IM_PITCH + bn + half * 16) * 2;
            uint32_t r0, r1, r2, r3;
            ldsm_x4_t(r0, r1, r2, r3, sb + oY + off);
            bhi[half * 2][0] = r0; bhi[half * 2][1] = r1;
            bhi[half * 2 + 1][0] = r2; bhi[half * 2 + 1][1] = r3;
            ldsm_x4_t(r0, r1, r2, r3, sb + oY + 9216 + off);
            bmid[half * 2][0] = r0; bmid[half * 2][1] = r1;
            bmid[half * 2 + 1][0] = r2; bmid[half * 2 + 1][1] = r3;
        }
        uint32_t ahi[4], amid[4];
        uint32_t off = (uint32_t)(arow * IM_PITCH + kk + akoff) * 2;
        ldsm_x4(ahi[0], ahi[1], ahi[2], ahi[3], sb + oX + off);
        ldsm_x4(amid[0], amid[1], amid[2], amid[3], sb + oX + 9216 + off);
#pragma unroll
        for (int ni = 0; ni < 4; ni++) {
            mma16816(acc[ni], ahi, bhi[ni]);
            mma16816(acc[ni], ahi, bmid[ni]);
            mma16816(acc[ni], amid, bhi[ni]);
        }
    }
}

__device__ __forceinline__ void inv_store(char* sm, uint32_t oX, uint32_t oZ,
                                          const float acc[4][4],
                                          float alpha, float beta, int lane, int wid) {
    int wm = wid >> 1, wn = wid & 1;
#pragma unroll
    for (int ni = 0; ni < 4; ni++)
#pragma unroll
        for (int rr = 0; rr < 2; rr++) {
            int row = wm * 16 + (lane >> 2) + rr * 8;
            int col = wn * 32 + ni * 8 + 2 * (lane & 3);
            uint32_t off = (uint32_t)(row * IM_PITCH + col) * 2;
            float2 xh = __bfloat1622float2(*(__nv_bfloat162*)(sm + oX + off));
            float2 xm = __bfloat1622float2(*(__nv_bfloat162*)(sm + oX + 9216 + off));
            float z0 = alpha * (xh.x + xm.x) - beta * acc[ni][rr * 2 + 0];
            float z1 = alpha * (xh.y + xm.y) - beta * acc[ni][rr * 2 + 1];
            store_bf16_pair((__nv_bfloat16*)(sm + oZ + off),
                            (__nv_bfloat16*)(sm + oZ + 9216 + off), z0, z1);
        }
}

__global__ __launch_bounds__(256) void inv_kernel() {
    extern __shared__ __align__(128) char sm[];
    __shared__ float sc[64][17];
    __shared__ float sinv[64];
    uint32_t sb = smem_u32(sm);
    int bh = blockIdx.x, tid = threadIdx.x;
    int lane = tid & 31, wid = tid >> 5;
    float ginv = 1.f / g_colmax;

    uint32_t oK = 0, oV = IM_MAT, oA = 2 * IM_MAT, oTa = 3 * IM_MAT, oTb = 4 * IM_MAT;

    if (tid < 64) {
        int row = tid;
        float2 st[KSPLIT];
        float m = -1e30f;
#pragma unroll
        for (int t = 0; t < KSPLIT; t++) {
            st[t] = g_stats[((size_t)bh * 64 + row) * KSPLIT + t];
            m = fmaxf(m, st[t].x);
        }
        float sum = 0.f;
#pragma unroll
        for (int t = 0; t < KSPLIT; t++) {
            float e = __expf(st[t].x - m);
            sc[row][t] = e;
            sum += e * st[t].y;
        }
        sinv[row] = 1.f / sum;
    }
    __syncthreads();

    for (int i = tid * 2; i < 4096; i += 512) {
        int r = i >> 6, c = i & 63;
        uint32_t off = (uint32_t)(r * IM_PITCH + c) * 2;
        float k0 = g_K2[bh * 4096 + r * 64 + c];
        float k1 = g_K2[bh * 4096 + r * 64 + c + 1];
        store_bf16_pair((__nv_bfloat16*)(sm + oK + off),
                        (__nv_bfloat16*)(sm + oK + 9216 + off), k0, k1);
        float v0 = g_K2[bh * 4096 + c * 64 + r] * ginv;
        float v1 = g_K2[bh * 4096 + (c + 1) * 64 + r] * ginv;
        store_bf16_pair((__nv_bfloat16*)(sm + oV + off),
                        (__nv_bfloat16*)(sm + oV + 9216 + off), v0, v1);
    }
    for (int i = tid; i < 4096; i += 256) {
        int r = i >> 6;
        float s = 0.f;
#pragma unroll
        for (int t = 0; t < KSPLIT; t++)
            s = fmaf(g_Tpart[(size_t)t * (BHN * MLAND * HD) + bh * 4096 + i], sc[r][t], s);
        g_W[bh * 4096 + i] = s * sinv[r];
    }

    for (int it = 0; it < 6; it++) {
        __syncthreads();
        {
            float acc[4][4] = {};
            inv_mm(sb, oK, oV, acc, lane, wid);
            inv_store(sm, oK, oA, acc, 0.0f, -1.0f, lane, wid);
        }
        __syncthreads();
        {
            float acc[4][4] = {};
            inv_mm(sb, oA, oA, acc, lane, wid);
            inv_store(sm, oA, oTa, acc, 7.0f, 1.0f, lane, wid);
        }
        __syncthreads();
        {
            float acc[4][4] = {};
            inv_mm(sb, oA, oTa, acc, lane, wid);
            inv_store(sm, oA, oTb, acc, 15.0f, 1.0f, lane, wid);
        }
        __syncthreads();
        {
            float acc[4][4] = {};
            inv_mm(sb, oV, oTb, acc, lane, wid);
            inv_store(sm, oV, oTa, acc, 3.25f, 0.25f, lane, wid);
        }
        uint32_t tmp = oV; oV = oTa; oTa = tmp;
    }
    __syncthreads();

    for (int i = tid * 2; i < 4096; i += 512) {
        int r = i >> 6, c = i & 63;
        uint32_t off = (uint32_t)(r * IM_PITCH + c) * 2;
        float t0 = g_W[bh * 4096 + i];
        float t1 = g_W[bh * 4096 + i + 1];
        store_bf16_pair((__nv_bfloat16*)(sm + oK + off),
                        (__nv_bfloat16*)(sm + oK + 9216 + off), t0, t1);
    }
    __syncthreads();

    {
        float acc[4][4] = {};
        inv_mm(sb, oV, oK, acc, lane, wid);
        int wm = wid >> 1, wn = wid & 1;
#pragma unroll
        for (int ni = 0; ni < 4; ni++)
#pragma unroll
            for (int rr = 0; rr < 2; rr++) {
                int row = wm * 16 + (lane >> 2) + rr * 8;
                int col = wn * 32 + ni * 8 + 2 * (lane & 3);
                size_t idx = (size_t)bh * 4096 + row * 64 + col;
                store_bf16_pair(g_Whi + idx, g_Wmid + idx,
                                acc[ni][rr * 2 + 0], acc[ni][rr * 2 + 1]);
            }
    }
}

// =====================================================================
// Final fused via tensor cores (ntoff = n-tile offset for halves)
// =====================================================================
#define FA_PITCH 72
#define FA_QH 0
#define FA_QM (64*FA_PITCH*2)
#define FA_BH (2*64*FA_PITCH*2)
#define FA_BM (3*64*FA_PITCH*2)
#define FA_SS (4*64*FA_PITCH*2)
#define FA_SMEM (FA_SS + 64*68*4)

__global__ __launch_bounds__(256) void final_attn(int ntoff) {
    extern __shared__ __align__(128) char sm[];
    uint32_t sb = smem_u32(sm);
    float* Ss = (float*)(sm + FA_SS);
    int nt = blockIdx.x + ntoff, bh = blockIdx.y, tid = threadIdx.x;
    int lane = tid & 31, wid = tid >> 5;
    int wm = wid >> 1, wn = wid & 1;
    int b = bh >> 3, h = bh & 7;

    const uint4* qh = (const uint4*)(g_Qhi + (((size_t)bh * NTOK) + nt * 64) * 64);
    const uint4* qm = (const uint4*)(g_Qmid + (((size_t)bh * NTOK) + nt * 64) * 64);
    const uint4* kh = (const uint4*)(g_Klh + bh * 4096);
    const uint4* km = (const uint4*)(g_Klm + bh * 4096);
#pragma unroll
    for (int it = 0; it < 2; it++) {
        int c = tid + it * 256;
        int row = c >> 3, col = (c & 7) * 8;
        uint32_t off = (uint32_t)(row * FA_PITCH + col) * 2;
        *(uint4*)(sm + FA_QH + off) = qh[c];
        *(uint4*)(sm + FA_QM + off) = qm[c];
        *(uint4*)(sm + FA_BH + off) = kh[c];
        *(uint4*)(sm + FA_BM + off) = km[c];
    }
    __syncthreads();

    int arow = wm * 16 + (lane & 15);
    int akoff = (lane >> 4) * 8;
    int brow = wn * 32 + (lane & 7) + ((lane >> 4) << 3);
    int bkoff = ((lane >> 3) & 1) * 8;

    float acc[4][4] = {};
#pragma unroll
    for (int kk = 0; kk < 64; kk += 16) {
        uint32_t bhi[4][2], bmid[4][2];
#pragma unroll
        for (int np = 0; np < 2; np++) {
            uint32_t off = (uint32_t)((brow + np * 16) * FA_PITCH + kk + bkoff) * 2;
            uint32_t r0, r1, r2, r3;
            ldsm_x4(r0, r1, r2, r3, sb + FA_BH + off);
            bhi[np * 2][0] = r0; bhi[np * 2][1] = r1;
            bhi[np * 2 + 1][0] = r2; bhi[np * 2 + 1][1] = r3;
            ldsm_x4(r0, r1, r2, r3, sb + FA_BM + off);
            bmid[np * 2][0] = r0; bmid[np * 2][1] = r1;
            bmid[np * 2 + 1][0] = r2; bmid[np * 2 + 1][1] = r3;
        }
        uint32_t ahi[4], amid[4];
        uint32_t off = (uint32_t)(arow * FA_PITCH + kk + akoff) * 2;
        ldsm_x4(ahi[0], ahi[1], ahi[2], ahi[3], sb + FA_QH + off);
        ldsm_x4(amid[0], amid[1], amid[2], amid[3], sb + FA_QM + off);
#pragma unroll
        for (int ni = 0; ni < 4; ni++) {
            mma16816(acc[ni], ahi, bhi[ni]);
            mma16816(acc[ni], ahi, bmid[ni]);
            mma16816(acc[ni], amid, bhi[ni]);
        }
    }
#pragma unroll
    for (int ni = 0; ni < 4; ni++)
#pragma unroll
        for (int rr = 0; rr < 2; rr++) {
            int row = wm * 16 + (lane >> 2) + rr * 8;
            int col = wn * 32 + ni * 8 + 2 * (lane & 3);
            Ss[row * 68 + col] = acc[ni][rr * 2 + 0];
            Ss[row * 68 + col + 1] = acc[ni][rr * 2 + 1];
        }
    __syncthreads();

    const uint4* wh = (const uint4*)(g_Whi + bh * 4096);
    const uint4* wmv = (const uint4*)(g_Wmid + bh * 4096);
#pragma unroll
    for (int it = 0; it < 2; it++) {
        int c = tid + it * 256;
        int row = c >> 3, col = (c & 7) * 8;
        uint32_t off = (uint32_t)(row * FA_PITCH + col) * 2;
        *(uint4*)(sm + FA_BH + off) = wh[c];
        *(uint4*)(sm + FA_BM + off) = wmv[c];
    }

    {
        int r = tid >> 2;
        int c0 = (tid & 3) * 16;
        float v[16];
        float mx = -1e30f;
#pragma unroll
        for (int j = 0; j < 16; j++) { v[j] = Ss[r * 68 + c0 + j]; mx = fmaxf(mx, v[j]); }
        mx = fmaxf(mx, __shfl_xor_sync(~0u, mx, 1, 4));
        mx = fmaxf(mx, __shfl_xor_sync(~0u, mx, 2, 4));
        float s = 0.f;
#pragma unroll
        for (int j = 0; j < 16; j++) { v[j] = __expf(v[j] - mx); s += v[j]; }
        s += __shfl_xor_sync(~0u, s, 1, 4);
        s += __shfl_xor_sync(~0u, s, 2, 4);
        float inv = 1.f / s;
#pragma unroll
        for (int j = 0; j < 16; j += 2) {
            float p0 = v[j] * inv, p1 = v[j + 1] * inv;
            uint32_t off = (uint32_t)(r * FA_PITCH + c0 + j) * 2;
            store_bf16_pair((__nv_bfloat16*)(sm + FA_QH + off),
                            (__nv_bfloat16*)(sm + FA_QM + off), p0, p1);
        }
    }
    __syncthreads();

    int bk = lane & 15;
    int bn = wn * 32 + ((lane >> 4) << 3);
    float acc2[4][4] = {};
#pragma unroll
    for (int kk = 0; kk < 64; kk += 16) {
        uint32_t bhi[4][2], bmid[4][2];
#pragma unroll
        for (int half = 0; half < 2; half++) {
            uint32_t off = (uint32_t)((kk + bk) * FA_PITCH + bn + half * 16) * 2;
            uint32_t r0, r1, r2, r3;
            ldsm_x4_t(r0, r1, r2, r3, sb + FA_BH + off);
            bhi[half * 2][0] = r0; bhi[half * 2][1] = r1;
            bhi[half * 2 + 1][0] = r2; bhi[half * 2 + 1][1] = r3;
            ldsm_x4_t(r0, r1, r2, r3, sb + FA_BM + off);
            bmid[half * 2][0] = r0; bmid[half * 2][1] = r1;
            bmid[half * 2 + 1][0] = r2; bmid[half * 2 + 1][1] = r3;
        }
        uint32_t ahi[4], amid[4];
        uint32_t off = (uint32_t)(arow * FA_PITCH + kk + akoff) * 2;
        ldsm_x4(ahi[0], ahi[1], ahi[2], ahi[3], sb + FA_QH + off);
        ldsm_x4(amid[0], amid[1], amid[2], amid[3], sb + FA_QM + off);
#pragma unroll
        for (int ni = 0; ni < 4; ni++) {
            mma16816(acc2[ni], ahi, bhi[ni]);
            mma16816(acc2[ni], ahi, bmid[ni]);
            mma16816(acc2[ni], amid, bhi[ni]);
        }
    }
#pragma unroll
    for (int ni = 0; ni < 4; ni++)
#pragma unroll
        for (int rr = 0; rr < 2; rr++) {
            int row = wm * 16 + (lane >> 2) + rr * 8;
            int col = wn * 32 + ni * 8 + 2 * (lane & 3);
            size_t idx = (((size_t)b * NTOK) + nt * 64 + row) * CDIM + h * 64 + col;
            store_bf16_pair(g_Xhi + idx, g_Xmid + idx,
                            acc2[ni][rr * 2 + 0], acc2[ni][rr * 2 + 1]);
        }
}

// =====================================================================
// host launcher: concurrent-stream head AND tail pipelining
// =====================================================================
extern "C" void kernel_launch(void* const* d_in, const int* in_sizes, int n_in,
                              void* d_out, int out_size) {
    const float* x      = (const float*)d_in[0];
    const float* qkv_w  = (const float*)d_in[1];
    const float* proj_w = (const float*)d_in[2];
    const float* proj_b = (const float*)d_in[3];
    float* out = (float*)d_out;

    static cudaStream_t s2 = nullptr;
    static cudaEvent_t ev1 = nullptr, evW = nullptr, evG1 = nullptr,
                       ev3 = nullptr, ev4 = nullptr, evI = nullptr, evT1 = nullptr;
    if (s2 == nullptr) {
        cudaStreamCreateWithFlags(&s2, cudaStreamNonBlocking);
        cudaEventCreateWithFlags(&ev1, cudaEventDisableTiming);
        cudaEventCreateWithFlags(&evW, cudaEventDisableTiming);
        cudaEventCreateWithFlags(&evG1, cudaEventDisableTiming);
        cudaEventCreateWithFlags(&ev3, cudaEventDisableTiming);
        cudaEventCreateWithFlags(&ev4, cudaEventDisableTiming);
        cudaEventCreateWithFlags(&evI, cudaEventDisableTiming);
        cudaEventCreateWithFlags(&evT1, cudaEventDisableTiming);
    }

    __nv_bfloat16 *xhi, *xmid, *whi, *wmid, *phi, *pmid, *Xhi, *Xmid;
    cudaGetSymbolAddress((void**)&xhi,  g_xhi);
    cudaGetSymbolAddress((void**)&xmid, g_xmid);
    cudaGetSymbolAddress((void**)&whi,  g_whi);
    cudaGetSymbolAddress((void**)&wmid, g_wmid);
    cudaGetSymbolAddress((void**)&phi,  g_phi);
    cudaGetSymbolAddress((void**)&pmid, g_pmid);
    cudaGetSymbolAddress((void**)&Xhi,  g_Xhi);
    cudaGetSymbolAddress((void**)&Xmid, g_Xmid);

    cudaFuncSetAttribute(hmma_gemm<0>, cudaFuncAttributeMaxDynamicSharedMemorySize, GEMM_SMEM);
    cudaFuncSetAttribute(hmma_gemm<1>, cudaFuncAttributeMaxDynamicSharedMemorySize, GEMM_SMEM);
    cudaFuncSetAttribute(attn3_fused, cudaFuncAttributeMaxDynamicSharedMemorySize, AT_SMEM);
    cudaFuncSetAttribute(final_attn, cudaFuncAttributeMaxDynamicSharedMemorySize, FA_SMEM);
    cudaFuncSetAttribute(inv_kernel, cudaFuncAttributeMaxDynamicSharedMemorySize, INV_SMEM);

    const int XH_N4 = 8192 * 512 / 4;
    const size_t XH_ELEM = (size_t)8192 * 512;

    // ---- head: both GEMM halves run CONCURRENTLY on different streams ----
    cudaEventRecord(ev1, 0);
    cudaStreamWaitEvent(s2, ev1, 0);
    split_kernel<<<768, 256, 0, s2>>>(qkv_w, whi, wmid, 1536 * 512 / 4);
    split_kernel<<<256, 256, 0, s2>>>(proj_w, phi, pmid, 512 * 512 / 4);
    cudaEventRecord(evW, s2);
    split_kernel<<<4096, 256, 0, s2>>>(x + XH_ELEM, xhi + XH_ELEM, xmid + XH_ELEM, XH_N4);
    hmma_gemm<0><<<dim3(12, 64), 256, GEMM_SMEM, s2>>>(xhi, xmid, whi, wmid,
                                                       nullptr, nullptr, 64, 0);
    cudaEventRecord(evG1, s2);
    split_kernel<<<4096, 256>>>(x, xhi, xmid, XH_N4);
    cudaStreamWaitEvent(0, evW, 0);
    hmma_gemm<0><<<dim3(12, 64), 256, GEMM_SMEM>>>(xhi, xmid, whi, wmid,
                                                   nullptr, nullptr, 0, 0);
    cudaStreamWaitEvent(0, evG1, 0);

    pool_kernel<<<BHN * MLAND, 64>>>();

    // ---- middle: k2 (s2) || attn3 (main) ----
    cudaEventRecord(ev3, 0);
    cudaStreamWaitEvent(s2, ev3, 0);
    k2_kernel<<<BHN, 256, 0, s2>>>();
    attn3_fused<<<dim3(KSPLIT, BHN), 256, AT_SMEM>>>();
    cudaEventRecord(ev4, s2);
    cudaStreamWaitEvent(0, ev4, 0);

    inv_kernel<<<BHN, 256, INV_SMEM>>>();
    cudaEventRecord(evI, 0);

    // ---- tail: concurrent halves — {final h1, hmma1 h1} on s2 || {final h0, hmma1 h0} on main
    cudaStreamWaitEvent(s2, evI, 0);
    final_attn<<<dim3(32, BHN), 256, FA_SMEM, s2>>>(32);
    hmma_gemm<1><<<dim3(4, 64), 256, GEMM_SMEM, s2>>>(Xhi, Xmid, phi, pmid,
                                                      proj_b, out, 16, 16);
    cudaEventRecord(evT1, s2);

    final_attn<<<dim3(32, BHN), 256, FA_SMEM>>>(0);
    hmma_gemm<1><<<dim3(4, 64), 256, GEMM_SMEM>>>(Xhi, Xmid, phi, pmid,
                                                  proj_b, out, 0, 16);
    cudaStreamWaitEvent(0, evT1, 0);
}